// round 8
// baseline (speedup 1.0000x reference)
#include <cuda_runtime.h>
#include <cstdint>

// ============================================================================
// Problem shapes:
//  x [8192,2048] f32 ; W1 [2048,8192] ; b1 [8192] ; W2 [8192,8192] ; b2 [8192]
//  out = fp8fakequant_gemm(gelu_tanh(fp8fakequant_gemm(x,W1)+b1), W2) + b2
//
// Math: blockwise fp8 fake-quant factors exactly:
//   C[m,n] = sum_kb sA[kb][m]*sB[kb][n] * ( sum_{k in kb} qA[m,k]*qB[n,k] )
// Inner sums run on fp8 tensor cores (mma.sync m16n8k32 e4m3, fp32 accum);
// scale promotion in CUDA-core fp32 (packed f32x2).
// ============================================================================
static constexpr int MROWS = 8192;
static constexpr int K1 = 2048, N1 = 8192;
static constexpr int K2 = 8192, N2 = 8192;

// ---------------------------------------------------------------------------
// Scratch (device globals; runtime allocation forbidden)
// ---------------------------------------------------------------------------
__device__ __align__(256) uint8_t g_xq [(size_t)MROWS * K1];      // [m][k]
__device__ __align__(256) float   g_sx [(K1 / 128) * MROWS];      // [kb][m]
__device__ __align__(256) uint8_t g_w1q[(size_t)N1 * K1];         // [n][k]
__device__ __align__(256) float   g_sw1[(K1 / 128) * N1];         // [kb][n]
__device__ __align__(256) uint8_t g_hq [(size_t)MROWS * N1];      // [m][k]
__device__ __align__(256) float   g_sh [(N1 / 128) * MROWS];      // [kb][m]
__device__ __align__(256) uint8_t g_w2q[(size_t)N2 * K2];         // [n][k]
__device__ __align__(256) float   g_sw2[(K2 / 128) * N2];         // [kb][n]

#define DINL __device__ __forceinline__

// ---------------------------------------------------------------------------
// Base-ISA PTX helpers
// ---------------------------------------------------------------------------
DINL uint32_t smem_u32(const void* p) {
    uint32_t a;
    asm("{ .reg .u64 t; cvta.to.shared.u64 t, %1; cvt.u32.u64 %0, t; }"
        : "=r"(a) : "l"(p));
    return a;
}

DINL void cp16(uint32_t dst, const void* src) {
    asm volatile("cp.async.cg.shared.global [%0], [%1], 16;"
                 :: "r"(dst), "l"(src) : "memory");
}
#define CP_COMMIT() asm volatile("cp.async.commit_group;" ::: "memory")
#define CP_WAIT1()  asm volatile("cp.async.wait_group 1;" ::: "memory")
#define CP_WAIT0()  asm volatile("cp.async.wait_group 0;" ::: "memory")

// e4m3x2 pack: low byte = a, high byte = b (RNE, saturate to +-448)
DINL uint16_t cvt2_e4m3(float a, float b) {
    uint16_t r;
    asm("cvt.rn.satfinite.e4m3x2.f32 %0, %1, %2;" : "=h"(r) : "f"(b), "f"(a));
    return r;
}

DINL void ldsm_x4(uint32_t* r, uint32_t addr) {
    asm volatile("ldmatrix.sync.aligned.m8n8.x4.shared.b16 {%0,%1,%2,%3}, [%4];"
        : "=r"(r[0]), "=r"(r[1]), "=r"(r[2]), "=r"(r[3]) : "r"(addr));
}

// fp8 warp MMA (base ISA): D(16x8,f32) += A(16x32,e4m3) * B(32x8,e4m3)
DINL void mma_fp8(float* d, const uint32_t* a, const uint32_t* b) {
    asm volatile(
        "mma.sync.aligned.m16n8k32.row.col.f32.e4m3.e4m3.f32 "
        "{%0,%1,%2,%3}, {%4,%5,%6,%7}, {%8,%9}, {%0,%1,%2,%3};"
        : "+f"(d[0]), "+f"(d[1]), "+f"(d[2]), "+f"(d[3])
        : "r"(a[0]), "r"(a[1]), "r"(a[2]), "r"(a[3]), "r"(b[0]), "r"(b[1]));
}
// zero-C variant: D = A*B (no accumulate, no pre-zeroing MOVs)
DINL void mma_fp8_zc(float* d, const uint32_t* a, const uint32_t* b) {
    asm volatile(
        "{\n\t.reg .f32 z;\n\tmov.f32 z, 0f00000000;\n\t"
        "mma.sync.aligned.m16n8k32.row.col.f32.e4m3.e4m3.f32 "
        "{%0,%1,%2,%3}, {%4,%5,%6,%7}, {%8,%9}, {z,z,z,z};\n\t}"
        : "=f"(d[0]), "=f"(d[1]), "=f"(d[2]), "=f"(d[3])
        : "r"(a[0]), "r"(a[1]), "r"(a[2]), "r"(a[3]), "r"(b[0]), "r"(b[1]));
}

// ---- packed f32x2 ----
DINL unsigned long long splat2(float a) {
    unsigned long long r;
    asm("mov.b64 %0, {%1, %1};" : "=l"(r) : "f"(a));
    return r;
}
DINL unsigned long long mul2(unsigned long long a, unsigned long long b) {
    unsigned long long r;
    asm("mul.rn.f32x2 %0, %1, %2;" : "=l"(r) : "l"(a), "l"(b));
    return r;
}
DINL void fma2(unsigned long long& d, unsigned long long c, float x, float y) {
    asm("{\n\t.reg .b64 B;\n\tmov.b64 B, {%2, %3};\n\t"
        "fma.rn.f32x2 %0, %1, B, %0;\n\t}"
        : "+l"(d) : "l"(c), "f"(x), "f"(y));
}
DINL void unpack2(unsigned long long v, float& lo, float& hi) {
    asm("mov.b64 {%0, %1}, %2;" : "=f"(lo), "=f"(hi) : "l"(v));
}

#define SW128B(off) ((off) ^ (((off) >> 3) & 0x70))

// ============================================================================
// Kernel 1: blockwise fp8 quant of activations along K (one warp per block)
// ============================================================================
__global__ void __launch_bounds__(256)
quant_rows_kernel(const float* __restrict__ x, int K,
                  uint8_t* __restrict__ xq, float* __restrict__ sx, int Mtot) {
    int gw = blockIdx.x * 8 + (threadIdx.x >> 5);
    int lane = threadIdx.x & 31;
    int KB = K / 128;
    int m = gw / KB, kb = gw % KB;
    if (m >= Mtot) return;
    const float4 v = *(const float4*)(x + (size_t)m * K + kb * 128 + lane * 4);
    float mx = fmaxf(fmaxf(fabsf(v.x), fabsf(v.y)), fmaxf(fabsf(v.z), fabsf(v.w)));
    #pragma unroll
    for (int o = 16; o; o >>= 1) mx = fmaxf(mx, __shfl_xor_sync(0xffffffffu, mx, o));
    float scale = __fdiv_rn(fmaxf(mx, 1e-12f), 448.0f);
    uint16_t lo = cvt2_e4m3(__fdiv_rn(v.x, scale), __fdiv_rn(v.y, scale));
    uint16_t hi = cvt2_e4m3(__fdiv_rn(v.z, scale), __fdiv_rn(v.w, scale));
    *(uint32_t*)(xq + (size_t)m * K + kb * 128 + lane * 4) =
        (uint32_t)lo | ((uint32_t)hi << 16);
    if (lane == 0) sx[(size_t)kb * Mtot + m] = scale;
}

// ============================================================================
// Kernel 2: blockwise fp8 quant of weights along K (axis 0) + transpose.
// Single gmem read: stage the 128x128 f32 tile in smem.
//   W [K, N] f32 -> wq [n][k] bytes, sw [kb][n]
// ============================================================================
static constexpr int QW_WF   = 0;                       // float [128][132]
static constexpr int QW_PM   = 128 * 132 * 4;           // float [2][128]
static constexpr int QW_SCL  = QW_PM + 256 * 4;         // float [128]
static constexpr int QW_BT   = QW_SCL + 128 * 4;        // u32   [128][33]
static constexpr int QW_SMEM = QW_BT + 128 * 33 * 4;    // 86016

__global__ void __launch_bounds__(256)
quant_wt_kernel(const float* __restrict__ w, int K, int N,
                uint8_t* __restrict__ wq, float* __restrict__ sw) {
    extern __shared__ __align__(16) uint8_t qsm[];
    float* wf  = (float*)(qsm + QW_WF);
    float* pm  = (float*)(qsm + QW_PM);
    float* scl = (float*)(qsm + QW_SCL);
    uint32_t* bt = (uint32_t*)(qsm + QW_BT);
    const int kb = blockIdx.y, n0 = blockIdx.x * 128;
    const int tid = threadIdx.x;
    const float* src = w + (size_t)(kb * 128) * N + n0;

    // stage tile: 4096 16B chunks
    #pragma unroll
    for (int i = 0; i < 16; i++) {
        int ch = i * 256 + tid;
        int k = ch >> 5, nc = ch & 31;
        cp16(smem_u32(wf + k * 132 + nc * 4), src + (size_t)k * N + nc * 4);
    }
    CP_COMMIT();
    CP_WAIT0();
    __syncthreads();

    const int c = tid & 127, h = tid >> 7;
    float mx = 0.f;
    for (int k = h * 64; k < h * 64 + 64; k++)
        mx = fmaxf(mx, fabsf(wf[k * 132 + c]));
    pm[h * 128 + c] = mx;
    __syncthreads();
    if (tid < 128) {
        float s = __fdiv_rn(fmaxf(fmaxf(pm[tid], pm[128 + tid]), 1e-12f), 448.0f);
        scl[tid] = s;
        sw[(size_t)kb * N + n0 + tid] = s;
    }
    __syncthreads();
    float s = scl[c];
    uint8_t* btb = (uint8_t*)bt;
    for (int k = h * 64; k < h * 64 + 64; k++)
        btb[c * 132 + k] = (uint8_t)cvt2_e4m3(__fdiv_rn(wf[k * 132 + c], s), 0.f);
    __syncthreads();
    #pragma unroll
    for (int i = 0; i < 16; i++) {
        int idx = i * 256 + tid;
        int r = idx >> 5, wd = idx & 31;
        ((uint32_t*)(wq + (size_t)(n0 + r) * K + (size_t)kb * 128))[wd] = bt[r * 33 + wd];
    }
}

// ============================================================================
// GEMM: 128x128 tile, 512 threads (4x4 warps, 32x32 per warp), mma.sync fp8.
// 3-stage cp.async pipeline, one __syncthreads per K-block, pointer-increment
// addressing, scales via direct LDG.
// EPI=0: out_f = C + bias          EPI=1: h=gelu(C+bias) -> fp8 quant out_q/s
// ============================================================================
static constexpr int NSTAGE = 3;
static constexpr int STAGE_BYTES = 32 * 1024;  // A 16K | B 16K
static constexpr int SM_HDR    = 1024;         // [64..576) bias
static constexpr int SM_B_OFF  = 16384;
static constexpr int EPI_F_OFF = 1024;                      // f32 tile [col][row] pad 129
static constexpr int EPI_B_OFF = 1024 + 128 * 129 * 4;      // u32 [128][33]
static constexpr int EPI_PM_OFF = EPI_B_OFF + 128 * 33 * 4; // float [5][128]
static constexpr int SMEM_GEMM = SM_HDR + NSTAGE * STAGE_BYTES;  // 99328 (> epi needs)

template <int EPI>
__global__ void __launch_bounds__(512, 1)
gemm_kernel(const uint8_t* __restrict__ Aq, const float* __restrict__ sA,
            const uint8_t* __restrict__ Bq, const float* __restrict__ sB,
            const float* __restrict__ bias, int K, int N,
            float* __restrict__ out_f,
            uint8_t* __restrict__ out_q, float* __restrict__ out_s) {
    extern __shared__ __align__(1024) uint8_t smem[];
    const uint32_t sbase = smem_u32(smem);
    const int tid = threadIdx.x;
    const int wid = tid >> 5, lane = tid & 31;
    const int wm = wid & 3, wn = wid >> 2;       // warp grid 4(M) x 4(N)
    const int g = lane >> 2, tig = lane & 3;     // mma group / thread-in-group
    const int n0 = blockIdx.x * 128, m0 = blockIdx.y * 128;
    const int NKB = K / 128;

    if (tid < 128) *(float*)(smem + 64 + tid * 4) = bias[n0 + tid];

    // packed accumulators: [mt][nt][kpair], each f32x2
    unsigned long long accp[2][4][2];
    #pragma unroll
    for (int mt = 0; mt < 2; mt++)
        #pragma unroll
        for (int nt = 0; nt < 4; nt++)
            #pragma unroll
            for (int p = 0; p < 2; p++) accp[mt][nt][p] = 0ull;

    // ---- pointer-increment prefetch state (computed once) ----
    const int prow = tid >> 3, pcol = tid & 7;   // each thread: rows prow, prow+64
    const uint8_t* pA0 = Aq + (size_t)(m0 + prow) * K + pcol * 16;
    const uint8_t* pA1 = pA0 + (size_t)64 * K;
    const uint8_t* pB0 = Bq + (size_t)(n0 + prow) * K + pcol * 16;
    const uint8_t* pB1 = pB0 + (size_t)64 * K;
    const uint32_t swlo = SW128B((uint32_t)(prow * 128 + pcol * 16));
    const uint32_t swhi = SW128B((uint32_t)((prow + 64) * 128 + pcol * 16));

    // scale pointers (direct LDG, immediate offsets; advance per kb)
    const float* psA = sA + m0 + wm * 32 + g;        // +{0,8,16,24}, stride MROWS
    const float* psB = sB + n0 + wn * 32 + tig * 2;  // +{0,8,16,24} (64-bit), stride N

    #define PREFETCH_STAGE(sidx) do {                                   \
        uint32_t _st = sbase + SM_HDR + (sidx) * STAGE_BYTES;           \
        cp16(_st + swlo, pA0);  cp16(_st + swhi, pA1);                  \
        cp16(_st + SM_B_OFF + swlo, pB0);                               \
        cp16(_st + SM_B_OFF + swhi, pB1);                               \
        pA0 += 128; pA1 += 128; pB0 += 128; pB1 += 128;                 \
    } while (0)

    PREFETCH_STAGE(0); CP_COMMIT();
    PREFETCH_STAGE(1); CP_COMMIT();

    // ---- hoisted ldmatrix addressing (stage-relative offsets) ----
    const int a_q = lane >> 3;
    const int rl  = lane & 7;
    uint32_t rowA[2], xcolA[4], rowB[2], xcolB[4];
    #pragma unroll
    for (int mt = 0; mt < 2; mt++)
        rowA[mt] = (uint32_t)((wm * 32 + mt * 16 + (a_q & 1) * 8 + rl) * 128);
    #pragma unroll
    for (int ks = 0; ks < 4; ks++)
        xcolA[ks] = (uint32_t)((ks * 32 + (a_q >> 1) * 16) ^ (rl << 4));
    // B pairs: x4 load np covers n-rows [np*16, np*16+16) of the warp block
    #pragma unroll
    for (int np = 0; np < 2; np++)
        rowB[np] = (uint32_t)((wn * 32 + np * 16 + ((lane >> 4) & 1) * 8 + rl) * 128);
    #pragma unroll
    for (int ks = 0; ks < 4; ks++)
        xcolB[ks] = (uint32_t)((ks * 32 + ((lane >> 3) & 1) * 16) ^ (rl << 4));

    int sidx = 0;   // stage of current kb
    for (int kb = 0; kb < NKB; kb++) {
        const uint32_t stA = sbase + SM_HDR + sidx * STAGE_BYTES;
        const uint32_t stB = stA + SM_B_OFF;

        CP_WAIT1();          // our stage-kb cp.async groups done (2 newer pending)
        __syncthreads();     // everyone's stage-kb data visible

        // early scale loads (registers; consumed after MMAs)
        float sa_f0 = psA[0],  sa_f1 = psA[8];
        float sa_f2 = psA[16], sa_f3 = psA[24];
        unsigned long long SB2[4];
        SB2[0] = *(const unsigned long long*)(psB + 0);
        SB2[1] = *(const unsigned long long*)(psB + 8);
        SB2[2] = *(const unsigned long long*)(psB + 16);
        SB2[3] = *(const unsigned long long*)(psB + 24);
        psA += MROWS; psB += N;

        // prefetch kb+2 into slot (kb+2)%3 (consumed at kb-1; safe post-sync)
        int sidx2 = sidx + 2 >= NSTAGE ? sidx + 2 - NSTAGE : sidx + 2;
        if (kb + 2 < NKB) PREFETCH_STAGE(sidx2);
        CP_COMMIT();         // unconditional: keeps wait_group accounting uniform

        float D[2][4][4];
        #pragma unroll
        for (int ks = 0; ks < 4; ks++) {
            uint32_t af[2][4], bq[2][4];
            #pragma unroll
            for (int mt = 0; mt < 2; mt++) ldsm_x4(af[mt], stA + rowA[mt] + xcolA[ks]);
            #pragma unroll
            for (int np = 0; np < 2; np++) ldsm_x4(bq[np], stB + rowB[np] + xcolB[ks]);
            #pragma unroll
            for (int mt = 0; mt < 2; mt++)
                #pragma unroll
                for (int nt = 0; nt < 4; nt++) {
                    const uint32_t* bf = &bq[nt >> 1][(nt & 1) * 2];
                    if (ks == 0) mma_fp8_zc(D[mt][nt], af[mt], bf);
                    else         mma_fp8   (D[mt][nt], af[mt], bf);
                }
        }

        // fine-grained scale promotion (packed f32x2): acc += (sa*sb) * D
        unsigned long long saS[2][2];
        saS[0][0] = splat2(sa_f0); saS[0][1] = splat2(sa_f1);
        saS[1][0] = splat2(sa_f2); saS[1][1] = splat2(sa_f3);
        #pragma unroll
        for (int mt = 0; mt < 2; mt++)
            #pragma unroll
            for (int nt = 0; nt < 4; nt++) {
                unsigned long long c01 = mul2(saS[mt][0], SB2[nt]);
                unsigned long long c23 = mul2(saS[mt][1], SB2[nt]);
                fma2(accp[mt][nt][0], c01, D[mt][nt][0], D[mt][nt][1]);
                fma2(accp[mt][nt][1], c23, D[mt][nt][2], D[mt][nt][3]);
            }

        sidx = sidx + 1 >= NSTAGE ? 0 : sidx + 1;
    }
    __syncthreads();   // mainloop smem dead; epilogue reuses it

    // ------------------------- epilogue -------------------------
    float* fb = (float*)(smem + EPI_F_OFF);   // [col][row], stride 129
    const float* biasS = (const float*)(smem + 64);
    #pragma unroll
    for (int mt = 0; mt < 2; mt++)
        #pragma unroll
        for (int nt = 0; nt < 4; nt++)
            #pragma unroll
            for (int p = 0; p < 2; p++) {
                float lo, hi;
                unpack2(accp[mt][nt][p], lo, hi);
                int row = wm * 32 + mt * 16 + p * 8 + g;
                int c0 = wn * 32 + nt * 8 + tig * 2;
                #pragma unroll
                for (int e = 0; e < 2; e++) {
                    int col = c0 + e;
                    float u = (e ? hi : lo) + biasS[col];
                    float v;
                    if (EPI == 1) {
                        float t = 0.7978845608028654f * (u + 0.044715f * u * u * u);
                        v = 0.5f * u * (1.0f + tanhf(t));
                    } else {
                        v = u;
                    }
                    fb[col * 129 + row] = v;
                }
            }
    __syncthreads();

    if (EPI == 0) {
        #pragma unroll
        for (int i = 0; i < 32; i++) {
            int idx = i * 512 + tid;
            int r = idx >> 7, c = idx & 127;
            out_f[(size_t)(m0 + r) * N + n0 + c] = fb[c * 129 + r];
        }
    } else {
        uint32_t* bt = (uint32_t*)(smem + EPI_B_OFF);
        float* pm = (float*)(smem + EPI_PM_OFF);          // [4][128] + scale [128]
        const int r = tid & 127, q = tid >> 7;            // 4 col-segments per row
        float mx = 0.f;
        #pragma unroll
        for (int c = q * 32; c < q * 32 + 32; c++) mx = fmaxf(mx, fabsf(fb[c * 129 + r]));
        pm[q * 128 + r] = mx;
        __syncthreads();
        if (tid < 128) {
            float m01 = fmaxf(pm[tid], pm[128 + tid]);
            float m23 = fmaxf(pm[256 + tid], pm[384 + tid]);
            float sc = __fdiv_rn(fmaxf(fmaxf(m01, m23), 1e-12f), 448.0f);
            pm[512 + tid] = sc;
            out_s[(size_t)(n0 >> 7) * MROWS + m0 + tid] = sc;
        }
        __syncthreads();
        float sc = pm[512 + r];
        #pragma unroll
        for (int c = q * 32; c < q * 32 + 32; c += 4) {
            uint16_t lo = cvt2_e4m3(__fdiv_rn(fb[(c + 0) * 129 + r], sc),
                                    __fdiv_rn(fb[(c + 1) * 129 + r], sc));
            uint16_t hi = cvt2_e4m3(__fdiv_rn(fb[(c + 2) * 129 + r], sc),
                                    __fdiv_rn(fb[(c + 3) * 129 + r], sc));
            bt[r * 33 + (c >> 2)] = (uint32_t)lo | ((uint32_t)hi << 16);
        }
        __syncthreads();
        #pragma unroll
        for (int i = 0; i < 8; i++) {
            int idx = i * 512 + tid;
            int rr = idx >> 5, wd = idx & 31;
            ((uint32_t*)(out_q + (size_t)(m0 + rr) * N + n0))[wd] = bt[rr * 33 + wd];
        }
    }
}

// ============================================================================
// Launch
// ============================================================================
extern "C" void kernel_launch(void* const* d_in, const int* in_sizes, int n_in,
                              void* d_out, int out_size) {
    const float* x  = (const float*)d_in[0];
    const float* w1 = (const float*)d_in[1];
    const float* b1 = (const float*)d_in[2];
    const float* w2 = (const float*)d_in[3];
    const float* b2 = (const float*)d_in[4];
    float* out = (float*)d_out;

    cudaFuncSetAttribute(gemm_kernel<0>, cudaFuncAttributeMaxDynamicSharedMemorySize, SMEM_GEMM);
    cudaFuncSetAttribute(gemm_kernel<1>, cudaFuncAttributeMaxDynamicSharedMemorySize, SMEM_GEMM);
    cudaFuncSetAttribute(quant_wt_kernel, cudaFuncAttributeMaxDynamicSharedMemorySize, QW_SMEM);

    uint8_t *xq, *w1q, *w2q, *hq;
    float *sx, *sw1, *sw2, *sh;
    cudaGetSymbolAddress((void**)&xq,  g_xq);
    cudaGetSymbolAddress((void**)&sx,  g_sx);
    cudaGetSymbolAddress((void**)&w1q, g_w1q);
    cudaGetSymbolAddress((void**)&sw1, g_sw1);
    cudaGetSymbolAddress((void**)&w2q, g_w2q);
    cudaGetSymbolAddress((void**)&sw2, g_sw2);
    cudaGetSymbolAddress((void**)&hq,  g_hq);
    cudaGetSymbolAddress((void**)&sh,  g_sh);

    // 1) quantize activations x
    quant_rows_kernel<<<(MROWS * (K1 / 128)) / 8, 256>>>(x, K1, xq, sx, MROWS);

    // 2) quantize + transpose weights (smem-staged single read)
    quant_wt_kernel<<<dim3(N1 / 128, K1 / 128), 256, QW_SMEM>>>(w1, K1, N1, w1q, sw1);
    quant_wt_kernel<<<dim3(N2 / 128, K2 / 128), 256, QW_SMEM>>>(w2, K2, N2, w2q, sw2);

    // 3) GEMM1 + bias + GELU + fused re-quant of h
    gemm_kernel<1><<<dim3(N1 / 128, MROWS / 128), 512, SMEM_GEMM>>>(
        xq, sx, w1q, sw1, b1, K1, N1, nullptr, hq, sh);

    // 4) GEMM2 + bias -> out
    gemm_kernel<0><<<dim3(N2 / 128, MROWS / 128), 512, SMEM_GEMM>>>(
        hq, sh, w2q, sw2, b2, K2, N2, out, nullptr, nullptr);
}

// round 9
// speedup vs baseline: 1.1403x; 1.1403x over previous
#include <cuda_runtime.h>
#include <cstdint>

// ============================================================================
// Problem shapes:
//  x [8192,2048] f32 ; W1 [2048,8192] ; b1 [8192] ; W2 [8192,8192] ; b2 [8192]
//  out = fp8fakequant_gemm(gelu_tanh(fp8fakequant_gemm(x,W1)+b1), W2) + b2
//
// Math: blockwise fp8 fake-quant factors exactly:
//   C[m,n] = sum_kb sA[kb][m]*sB[kb][n] * ( sum_{k in kb} qA[m,k]*qB[n,k] )
// Inner sums on fp8 tensor cores (mma.sync m16n8k32 e4m3, fp32 accum);
// scale promotion in CUDA-core fp32 (packed f32x2).
// R9: 256-thread CTAs (2 CTAs/SM) with rectangular tiles:
//   GEMM1: 64x128 (re-quant block N=128 stays in-tile), GEMM2: 128x64.
// ============================================================================
static constexpr int MROWS = 8192;
static constexpr int K1 = 2048, N1 = 8192;
static constexpr int K2 = 8192, N2 = 8192;

// ---------------------------------------------------------------------------
// Scratch (device globals; runtime allocation forbidden)
// ---------------------------------------------------------------------------
__device__ __align__(256) uint8_t g_xq [(size_t)MROWS * K1];      // [m][k]
__device__ __align__(256) float   g_sx [(K1 / 128) * MROWS];      // [kb][m]
__device__ __align__(256) uint8_t g_w1q[(size_t)N1 * K1];         // [n][k]
__device__ __align__(256) float   g_sw1[(K1 / 128) * N1];         // [kb][n]
__device__ __align__(256) uint8_t g_hq [(size_t)MROWS * N1];      // [m][k]
__device__ __align__(256) float   g_sh [(N1 / 128) * MROWS];      // [kb][m]
__device__ __align__(256) uint8_t g_w2q[(size_t)N2 * K2];         // [n][k]
__device__ __align__(256) float   g_sw2[(K2 / 128) * N2];         // [kb][n]

#define DINL __device__ __forceinline__

// ---------------------------------------------------------------------------
// Base-ISA PTX helpers
// ---------------------------------------------------------------------------
DINL uint32_t smem_u32(const void* p) {
    uint32_t a;
    asm("{ .reg .u64 t; cvta.to.shared.u64 t, %1; cvt.u32.u64 %0, t; }"
        : "=r"(a) : "l"(p));
    return a;
}

DINL void cp16(uint32_t dst, const void* src) {
    asm volatile("cp.async.cg.shared.global [%0], [%1], 16;"
                 :: "r"(dst), "l"(src) : "memory");
}
#define CP_COMMIT() asm volatile("cp.async.commit_group;" ::: "memory")
#define CP_WAIT1()  asm volatile("cp.async.wait_group 1;" ::: "memory")
#define CP_WAIT0()  asm volatile("cp.async.wait_group 0;" ::: "memory")

// e4m3x2 pack: low byte = a, high byte = b (RNE, saturate to +-448)
DINL uint16_t cvt2_e4m3(float a, float b) {
    uint16_t r;
    asm("cvt.rn.satfinite.e4m3x2.f32 %0, %1, %2;" : "=h"(r) : "f"(b), "f"(a));
    return r;
}

DINL void ldsm_x4(uint32_t* r, uint32_t addr) {
    asm volatile("ldmatrix.sync.aligned.m8n8.x4.shared.b16 {%0,%1,%2,%3}, [%4];"
        : "=r"(r[0]), "=r"(r[1]), "=r"(r[2]), "=r"(r[3]) : "r"(addr));
}

// fp8 warp MMA (base ISA): D(16x8,f32) += A(16x32,e4m3) * B(32x8,e4m3)
DINL void mma_fp8(float* d, const uint32_t* a, const uint32_t* b) {
    asm volatile(
        "mma.sync.aligned.m16n8k32.row.col.f32.e4m3.e4m3.f32 "
        "{%0,%1,%2,%3}, {%4,%5,%6,%7}, {%8,%9}, {%0,%1,%2,%3};"
        : "+f"(d[0]), "+f"(d[1]), "+f"(d[2]), "+f"(d[3])
        : "r"(a[0]), "r"(a[1]), "r"(a[2]), "r"(a[3]), "r"(b[0]), "r"(b[1]));
}
// zero-C variant: D = A*B (no accumulate, no pre-zeroing MOVs)
DINL void mma_fp8_zc(float* d, const uint32_t* a, const uint32_t* b) {
    asm volatile(
        "{\n\t.reg .f32 z;\n\tmov.f32 z, 0f00000000;\n\t"
        "mma.sync.aligned.m16n8k32.row.col.f32.e4m3.e4m3.f32 "
        "{%0,%1,%2,%3}, {%4,%5,%6,%7}, {%8,%9}, {z,z,z,z};\n\t}"
        : "=f"(d[0]), "=f"(d[1]), "=f"(d[2]), "=f"(d[3])
        : "r"(a[0]), "r"(a[1]), "r"(a[2]), "r"(a[3]), "r"(b[0]), "r"(b[1]));
}

// ---- packed f32x2 ----
DINL unsigned long long splat2(float a) {
    unsigned long long r;
    asm("mov.b64 %0, {%1, %1};" : "=l"(r) : "f"(a));
    return r;
}
DINL unsigned long long mul2(unsigned long long a, unsigned long long b) {
    unsigned long long r;
    asm("mul.rn.f32x2 %0, %1, %2;" : "=l"(r) : "l"(a), "l"(b));
    return r;
}
DINL void fma2(unsigned long long& d, unsigned long long c, float x, float y) {
    asm("{\n\t.reg .b64 B;\n\tmov.b64 B, {%2, %3};\n\t"
        "fma.rn.f32x2 %0, %1, B, %0;\n\t}"
        : "+l"(d) : "l"(c), "f"(x), "f"(y));
}
DINL void unpack2(unsigned long long v, float& lo, float& hi) {
    asm("mov.b64 {%0, %1}, %2;" : "=f"(lo), "=f"(hi) : "l"(v));
}

#define SW128B(off) ((off) ^ (((off) >> 3) & 0x70))

// ============================================================================
// Kernel 1: blockwise fp8 quant of activations along K (one warp per block)
// ============================================================================
__global__ void __launch_bounds__(256)
quant_rows_kernel(const float* __restrict__ x, int K,
                  uint8_t* __restrict__ xq, float* __restrict__ sx, int Mtot) {
    int gw = blockIdx.x * 8 + (threadIdx.x >> 5);
    int lane = threadIdx.x & 31;
    int KB = K / 128;
    int m = gw / KB, kb = gw % KB;
    if (m >= Mtot) return;
    const float4 v = *(const float4*)(x + (size_t)m * K + kb * 128 + lane * 4);
    float mx = fmaxf(fmaxf(fabsf(v.x), fabsf(v.y)), fmaxf(fabsf(v.z), fabsf(v.w)));
    #pragma unroll
    for (int o = 16; o; o >>= 1) mx = fmaxf(mx, __shfl_xor_sync(0xffffffffu, mx, o));
    float scale = __fdiv_rn(fmaxf(mx, 1e-12f), 448.0f);
    uint16_t lo = cvt2_e4m3(__fdiv_rn(v.x, scale), __fdiv_rn(v.y, scale));
    uint16_t hi = cvt2_e4m3(__fdiv_rn(v.z, scale), __fdiv_rn(v.w, scale));
    *(uint32_t*)(xq + (size_t)m * K + kb * 128 + lane * 4) =
        (uint32_t)lo | ((uint32_t)hi << 16);
    if (lane == 0) sx[(size_t)kb * Mtot + m] = scale;
}

// ============================================================================
// Kernel 2: blockwise fp8 quant of weights along K (axis 0) + transpose.
//   W [K, N] f32 -> wq [n][k] bytes, sw [kb][n]
// ============================================================================
static constexpr int QW_WF   = 0;                       // float [128][132]
static constexpr int QW_PM   = 128 * 132 * 4;           // float [2][128]
static constexpr int QW_SCL  = QW_PM + 256 * 4;         // float [128]
static constexpr int QW_BT   = QW_SCL + 128 * 4;        // u32   [128][33]
static constexpr int QW_SMEM = QW_BT + 128 * 33 * 4;    // 86016

__global__ void __launch_bounds__(256)
quant_wt_kernel(const float* __restrict__ w, int K, int N,
                uint8_t* __restrict__ wq, float* __restrict__ sw) {
    extern __shared__ __align__(16) uint8_t qsm[];
    float* wf  = (float*)(qsm + QW_WF);
    float* pm  = (float*)(qsm + QW_PM);
    float* scl = (float*)(qsm + QW_SCL);
    uint32_t* bt = (uint32_t*)(qsm + QW_BT);
    const int kb = blockIdx.y, n0 = blockIdx.x * 128;
    const int tid = threadIdx.x;
    const float* src = w + (size_t)(kb * 128) * N + n0;

    #pragma unroll
    for (int i = 0; i < 16; i++) {
        int ch = i * 256 + tid;
        int k = ch >> 5, nc = ch & 31;
        cp16(smem_u32(wf + k * 132 + nc * 4), src + (size_t)k * N + nc * 4);
    }
    CP_COMMIT();
    CP_WAIT0();
    __syncthreads();

    const int c = tid & 127, h = tid >> 7;
    float mx = 0.f;
    for (int k = h * 64; k < h * 64 + 64; k++)
        mx = fmaxf(mx, fabsf(wf[k * 132 + c]));
    pm[h * 128 + c] = mx;
    __syncthreads();
    if (tid < 128) {
        float s = __fdiv_rn(fmaxf(fmaxf(pm[tid], pm[128 + tid]), 1e-12f), 448.0f);
        scl[tid] = s;
        sw[(size_t)kb * N + n0 + tid] = s;
    }
    __syncthreads();
    float s = scl[c];
    uint8_t* btb = (uint8_t*)bt;
    for (int k = h * 64; k < h * 64 + 64; k++)
        btb[c * 132 + k] = (uint8_t)cvt2_e4m3(__fdiv_rn(wf[k * 132 + c], s), 0.f);
    __syncthreads();
    #pragma unroll
    for (int i = 0; i < 16; i++) {
        int idx = i * 256 + tid;
        int r = idx >> 5, wd = idx & 31;
        ((uint32_t*)(wq + (size_t)(n0 + r) * K + (size_t)kb * 128))[wd] = bt[r * 33 + wd];
    }
}

// ============================================================================
// GEMM: BM x BN tile, 256 threads (warp grid (BM/32) x (BN/32), 32x32/warp),
// mma.sync fp8, 2-stage cp.async double buffer (R7-proven loop structure),
// 2 CTAs/SM.  EPI=0 (BM=128,BN=64): out_f = C + bias.
//             EPI=1 (BM=64,BN=128): h=gelu(C+bias) -> fp8 quant out_q/out_s.
// ============================================================================
static constexpr int STAGE = 25600;            // A BM*128 | B BN*128 | sA | sB
static constexpr int SM_HDR = 1024;            // [64..576) bias
static constexpr int SMEM_GEMM = SM_HDR + 2 * STAGE;   // 52224

template <int EPI>
__global__ void __launch_bounds__(256, 2)
gemm_kernel(const uint8_t* __restrict__ Aq, const float* __restrict__ sA,
            const uint8_t* __restrict__ Bq, const float* __restrict__ sB,
            const float* __restrict__ bias, int K, int N,
            float* __restrict__ out_f,
            uint8_t* __restrict__ out_q, float* __restrict__ out_s) {
    constexpr int BM = EPI ? 64 : 128;
    constexpr int BN = EPI ? 128 : 64;
    constexpr int WM = BM / 32;                 // warps along M
    constexpr int SM_B  = BM * 128;
    constexpr int SM_SA = (BM + BN) * 128;
    constexpr int SM_SB = SM_SA + BM * 4;

    extern __shared__ __align__(1024) uint8_t smem[];
    const uint32_t sbase = smem_u32(smem);
    const int tid = threadIdx.x;
    const int wid = tid >> 5, lane = tid & 31;
    const int wm = wid % WM, wn = wid / WM;
    const int g = lane >> 2, tig = lane & 3;
    const int n0 = blockIdx.x * BN, m0 = blockIdx.y * BM;
    const int NKB = K / 128;

    if (tid < BN) *(float*)(smem + 64 + tid * 4) = bias[n0 + tid];

    unsigned long long accp[2][4][2];
    #pragma unroll
    for (int mt = 0; mt < 2; mt++)
        #pragma unroll
        for (int nt = 0; nt < 4; nt++)
            #pragma unroll
            for (int p = 0; p < 2; p++) accp[mt][nt][p] = 0ull;

    // ---- pointer-increment prefetch state ----
    const int prow = tid >> 3, pcol = tid & 7;   // rows prow + 32*i
    const uint8_t* pA = Aq + (size_t)(m0 + prow) * K + pcol * 16;
    const uint8_t* pB = Bq + (size_t)(n0 + prow) * K + pcol * 16;
    const float* psAg = sA + m0 + tid * 4;             // tid < BM/4
    const float* psBg = sB + n0 + (tid - 128) * 4;     // 128 <= tid < 128+BN/4
    uint32_t swA[BM / 32], swB[BN / 32];
    #pragma unroll
    for (int i = 0; i < BM / 32; i++)
        swA[i] = SW128B((uint32_t)((prow + 32 * i) * 128 + pcol * 16));
    #pragma unroll
    for (int i = 0; i < BN / 32; i++)
        swB[i] = SW128B((uint32_t)((prow + 32 * i) * 128 + pcol * 16));

    auto prefetch = [&](int stg) {
        uint32_t st = sbase + SM_HDR + stg * STAGE;
        #pragma unroll
        for (int i = 0; i < BM / 32; i++)
            cp16(st + swA[i], pA + (size_t)(32 * i) * K);
        #pragma unroll
        for (int i = 0; i < BN / 32; i++)
            cp16(st + SM_B + swB[i], pB + (size_t)(32 * i) * K);
        if (tid < BM / 4)
            cp16(st + SM_SA + tid * 16, psAg);
        else if (tid >= 128 && tid < 128 + BN / 4)
            cp16(st + SM_SB + (tid - 128) * 16, psBg);
        pA += 128; pB += 128; psAg += MROWS; psBg += N;
    };

    prefetch(0);
    CP_COMMIT();

    // ---- hoisted ldmatrix addressing (stage-relative offsets) ----
    const int a_q = lane >> 3;
    const int rl  = lane & 7;
    uint32_t rowA[2], xcolA[4], rowB[2], xcolB[4];
    #pragma unroll
    for (int mt = 0; mt < 2; mt++)
        rowA[mt] = (uint32_t)((wm * 32 + mt * 16 + (a_q & 1) * 8 + rl) * 128);
    #pragma unroll
    for (int ks = 0; ks < 4; ks++)
        xcolA[ks] = (uint32_t)((ks * 32 + (a_q >> 1) * 16) ^ (rl << 4));
    // B pairs: x4 load np covers n-rows [np*16, np*16+16) of the warp block
    #pragma unroll
    for (int np = 0; np < 2; np++)
        rowB[np] = (uint32_t)((wn * 32 + np * 16 + ((lane >> 4) & 1) * 8 + rl) * 128);
    #pragma unroll
    for (int ks = 0; ks < 4; ks++)
        xcolB[ks] = (uint32_t)((ks * 32 + ((lane >> 3) & 1) * 16) ^ (rl << 4));

    for (int kb = 0; kb < NKB; kb++) {
        const int s = kb & 1;
        const uint32_t stA = sbase + SM_HDR + s * STAGE;
        const uint32_t stB = stA + SM_B;

        if (kb + 1 < NKB) prefetch(s ^ 1);
        CP_COMMIT();
        CP_WAIT1();
        __syncthreads();

        float D[2][4][4];
        #pragma unroll
        for (int ks = 0; ks < 4; ks++) {
            uint32_t af[2][4], bq[2][4];
            #pragma unroll
            for (int mt = 0; mt < 2; mt++) ldsm_x4(af[mt], stA + rowA[mt] + xcolA[ks]);
            #pragma unroll
            for (int np = 0; np < 2; np++) ldsm_x4(bq[np], stB + rowB[np] + xcolB[ks]);
            #pragma unroll
            for (int mt = 0; mt < 2; mt++)
                #pragma unroll
                for (int nt = 0; nt < 4; nt++) {
                    const uint32_t* bf = &bq[nt >> 1][(nt & 1) * 2];
                    if (ks == 0) mma_fp8_zc(D[mt][nt], af[mt], bf);
                    else         mma_fp8   (D[mt][nt], af[mt], bf);
                }
        }

        // fine-grained scale promotion (packed f32x2): acc += (sa*sb) * D
        const uint8_t* sAs = smem + SM_HDR + s * STAGE + SM_SA;
        const uint8_t* sBs = smem + SM_HDR + s * STAGE + SM_SB;
        unsigned long long SB2[4], saS[2][2];
        #pragma unroll
        for (int nt = 0; nt < 4; nt++)
            SB2[nt] = *(const unsigned long long*)(sBs + (wn * 32 + nt * 8 + tig * 2) * 4);
        #pragma unroll
        for (int mt = 0; mt < 2; mt++)
            #pragma unroll
            for (int j = 0; j < 2; j++)
                saS[mt][j] = splat2(*(const float*)(sAs + (wm * 32 + mt * 16 + j * 8 + g) * 4));
        #pragma unroll
        for (int mt = 0; mt < 2; mt++)
            #pragma unroll
            for (int nt = 0; nt < 4; nt++) {
                unsigned long long c01 = mul2(saS[mt][0], SB2[nt]);
                unsigned long long c23 = mul2(saS[mt][1], SB2[nt]);
                fma2(accp[mt][nt][0], c01, D[mt][nt][0], D[mt][nt][1]);
                fma2(accp[mt][nt][1], c23, D[mt][nt][2], D[mt][nt][3]);
            }
        __syncthreads();
    }

    // ------------------------- epilogue -------------------------
    constexpr int FBS = BM + 1;                 // fb stride ([col][row])
    float* fb = (float*)(smem + SM_HDR);
    const float* biasS = (const float*)(smem + 64);
    #pragma unroll
    for (int mt = 0; mt < 2; mt++)
        #pragma unroll
        for (int nt = 0; nt < 4; nt++)
            #pragma unroll
            for (int p = 0; p < 2; p++) {
                float lo, hi;
                unpack2(accp[mt][nt][p], lo, hi);
                int row = wm * 32 + mt * 16 + p * 8 + g;
                int c0 = wn * 32 + nt * 8 + tig * 2;
                #pragma unroll
                for (int e = 0; e < 2; e++) {
                    int col = c0 + e;
                    float u = (e ? hi : lo) + biasS[col];
                    float v;
                    if (EPI == 1) {
                        float t = 0.7978845608028654f * (u + 0.044715f * u * u * u);
                        v = 0.5f * u * (1.0f + tanhf(t));
                    } else {
                        v = u;
                    }
                    fb[col * FBS + row] = v;
                }
            }
    __syncthreads();

    if (EPI == 0) {
        // BM=128, BN=64: write 8192 floats, 32 per thread
        #pragma unroll
        for (int i = 0; i < 32; i++) {
            int idx = i * 256 + tid;
            int r = idx >> 6, c = idx & 63;
            out_f[(size_t)(m0 + r) * N + n0 + c] = fb[c * FBS + r];
        }
    } else {
        // BM=64, BN=128: blockwise re-quant of h along the 128 cols
        uint32_t* bt = (uint32_t*)(smem + SM_HDR + 128 * FBS * 4);     // [64][33]
        float* pm = (float*)((uint8_t*)bt + 64 * 33 * 4);              // [4][64]+[64]
        const int r = tid & 63, q = tid >> 6;        // 4 col-segments of 32
        float mx = 0.f;
        #pragma unroll
        for (int c = q * 32; c < q * 32 + 32; c++) mx = fmaxf(mx, fabsf(fb[c * FBS + r]));
        pm[q * 64 + r] = mx;
        __syncthreads();
        if (tid < 64) {
            float m01 = fmaxf(pm[tid], pm[64 + tid]);
            float m23 = fmaxf(pm[128 + tid], pm[192 + tid]);
            float sc = __fdiv_rn(fmaxf(fmaxf(m01, m23), 1e-12f), 448.0f);
            pm[256 + tid] = sc;
            out_s[(size_t)(n0 >> 7) * MROWS + m0 + tid] = sc;
        }
        __syncthreads();
        float sc = pm[256 + r];
        #pragma unroll
        for (int c = q * 32; c < q * 32 + 32; c += 4) {
            uint16_t lo = cvt2_e4m3(__fdiv_rn(fb[(c + 0) * FBS + r], sc),
                                    __fdiv_rn(fb[(c + 1) * FBS + r], sc));
            uint16_t hi = cvt2_e4m3(__fdiv_rn(fb[(c + 2) * FBS + r], sc),
                                    __fdiv_rn(fb[(c + 3) * FBS + r], sc));
            bt[r * 33 + (c >> 2)] = (uint32_t)lo | ((uint32_t)hi << 16);
        }
        __syncthreads();
        // store 64 rows x 32 words, 8 per thread
        #pragma unroll
        for (int i = 0; i < 8; i++) {
            int idx = i * 256 + tid;
            int rr = idx >> 5, wd = idx & 31;
            ((uint32_t*)(out_q + (size_t)(m0 + rr) * N + n0))[wd] = bt[rr * 33 + wd];
        }
    }
}

// ============================================================================
// Launch
// ============================================================================
extern "C" void kernel_launch(void* const* d_in, const int* in_sizes, int n_in,
                              void* d_out, int out_size) {
    const float* x  = (const float*)d_in[0];
    const float* w1 = (const float*)d_in[1];
    const float* b1 = (const float*)d_in[2];
    const float* w2 = (const float*)d_in[3];
    const float* b2 = (const float*)d_in[4];
    float* out = (float*)d_out;

    cudaFuncSetAttribute(gemm_kernel<0>, cudaFuncAttributeMaxDynamicSharedMemorySize, SMEM_GEMM);
    cudaFuncSetAttribute(gemm_kernel<1>, cudaFuncAttributeMaxDynamicSharedMemorySize, SMEM_GEMM);
    cudaFuncSetAttribute(quant_wt_kernel, cudaFuncAttributeMaxDynamicSharedMemorySize, QW_SMEM);

    uint8_t *xq, *w1q, *w2q, *hq;
    float *sx, *sw1, *sw2, *sh;
    cudaGetSymbolAddress((void**)&xq,  g_xq);
    cudaGetSymbolAddress((void**)&sx,  g_sx);
    cudaGetSymbolAddress((void**)&w1q, g_w1q);
    cudaGetSymbolAddress((void**)&sw1, g_sw1);
    cudaGetSymbolAddress((void**)&w2q, g_w2q);
    cudaGetSymbolAddress((void**)&sw2, g_sw2);
    cudaGetSymbolAddress((void**)&hq,  g_hq);
    cudaGetSymbolAddress((void**)&sh,  g_sh);

    // 1) quantize activations x
    quant_rows_kernel<<<(MROWS * (K1 / 128)) / 8, 256>>>(x, K1, xq, sx, MROWS);

    // 2) quantize + transpose weights (smem-staged single read)
    quant_wt_kernel<<<dim3(N1 / 128, K1 / 128), 256, QW_SMEM>>>(w1, K1, N1, w1q, sw1);
    quant_wt_kernel<<<dim3(N2 / 128, K2 / 128), 256, QW_SMEM>>>(w2, K2, N2, w2q, sw2);

    // 3) GEMM1 (64x128 tiles) + bias + GELU + fused re-quant of h
    gemm_kernel<1><<<dim3(N1 / 128, MROWS / 64), 256, SMEM_GEMM>>>(
        xq, sx, w1q, sw1, b1, K1, N1, nullptr, hq, sh);

    // 4) GEMM2 (128x64 tiles) + bias -> out
    gemm_kernel<0><<<dim3(N2 / 64, MROWS / 128), 256, SMEM_GEMM>>>(
        hq, sh, w2q, sw2, b2, K2, N2, out, nullptr, nullptr);
}

// round 10
// speedup vs baseline: 1.1525x; 1.0107x over previous
#include <cuda_runtime.h>
#include <cstdint>

// ============================================================================
// Problem shapes:
//  x [8192,2048] f32 ; W1 [2048,8192] ; b1 [8192] ; W2 [8192,8192] ; b2 [8192]
//  out = fp8fakequant_gemm(gelu_tanh(fp8fakequant_gemm(x,W1)+b1), W2) + b2
//
// Math: blockwise fp8 fake-quant factors exactly:
//   C[m,n] = sum_kb sA[kb][m]*sB[kb][n] * ( sum_{k in kb} qA[m,k]*qB[n,k] )
// Inner sums on fp8 tensor cores (mma.sync m16n8k32 e4m3, fp32 accum);
// scale promotion in CUDA-core fp32 (packed f32x2).
// R10: 3-stage cp.async pipeline with ONE __syncthreads per K-block
//      (prefetch issued post-sync into the provably-free slot), scales
//      staged via cp.async; 256-thread CTAs (2 CTAs/SM), rectangular tiles.
// ============================================================================
static constexpr int MROWS = 8192;
static constexpr int K1 = 2048, N1 = 8192;
static constexpr int K2 = 8192, N2 = 8192;

// ---------------------------------------------------------------------------
// Scratch (device globals; runtime allocation forbidden)
// ---------------------------------------------------------------------------
__device__ __align__(256) uint8_t g_xq [(size_t)MROWS * K1];      // [m][k]
__device__ __align__(256) float   g_sx [(K1 / 128) * MROWS];      // [kb][m]
__device__ __align__(256) uint8_t g_w1q[(size_t)N1 * K1];         // [n][k]
__device__ __align__(256) float   g_sw1[(K1 / 128) * N1];         // [kb][n]
__device__ __align__(256) uint8_t g_hq [(size_t)MROWS * N1];      // [m][k]
__device__ __align__(256) float   g_sh [(N1 / 128) * MROWS];      // [kb][m]
__device__ __align__(256) uint8_t g_w2q[(size_t)N2 * K2];         // [n][k]
__device__ __align__(256) float   g_sw2[(K2 / 128) * N2];         // [kb][n]

#define DINL __device__ __forceinline__

// ---------------------------------------------------------------------------
// Base-ISA PTX helpers
// ---------------------------------------------------------------------------
DINL uint32_t smem_u32(const void* p) {
    uint32_t a;
    asm("{ .reg .u64 t; cvta.to.shared.u64 t, %1; cvt.u32.u64 %0, t; }"
        : "=r"(a) : "l"(p));
    return a;
}

DINL void cp16(uint32_t dst, const void* src) {
    asm volatile("cp.async.cg.shared.global [%0], [%1], 16;"
                 :: "r"(dst), "l"(src) : "memory");
}
#define CP_COMMIT() asm volatile("cp.async.commit_group;" ::: "memory")
#define CP_WAIT1()  asm volatile("cp.async.wait_group 1;" ::: "memory")
#define CP_WAIT0()  asm volatile("cp.async.wait_group 0;" ::: "memory")

// e4m3x2 pack: low byte = a, high byte = b (RNE, saturate to +-448)
DINL uint16_t cvt2_e4m3(float a, float b) {
    uint16_t r;
    asm("cvt.rn.satfinite.e4m3x2.f32 %0, %1, %2;" : "=h"(r) : "f"(b), "f"(a));
    return r;
}

DINL void ldsm_x4(uint32_t* r, uint32_t addr) {
    asm volatile("ldmatrix.sync.aligned.m8n8.x4.shared.b16 {%0,%1,%2,%3}, [%4];"
        : "=r"(r[0]), "=r"(r[1]), "=r"(r[2]), "=r"(r[3]) : "r"(addr));
}

// fp8 warp MMA (base ISA): D(16x8,f32) += A(16x32,e4m3) * B(32x8,e4m3)
DINL void mma_fp8(float* d, const uint32_t* a, const uint32_t* b) {
    asm volatile(
        "mma.sync.aligned.m16n8k32.row.col.f32.e4m3.e4m3.f32 "
        "{%0,%1,%2,%3}, {%4,%5,%6,%7}, {%8,%9}, {%0,%1,%2,%3};"
        : "+f"(d[0]), "+f"(d[1]), "+f"(d[2]), "+f"(d[3])
        : "r"(a[0]), "r"(a[1]), "r"(a[2]), "r"(a[3]), "r"(b[0]), "r"(b[1]));
}
// zero-C variant: D = A*B (no accumulate, no pre-zeroing MOVs)
DINL void mma_fp8_zc(float* d, const uint32_t* a, const uint32_t* b) {
    asm volatile(
        "{\n\t.reg .f32 z;\n\tmov.f32 z, 0f00000000;\n\t"
        "mma.sync.aligned.m16n8k32.row.col.f32.e4m3.e4m3.f32 "
        "{%0,%1,%2,%3}, {%4,%5,%6,%7}, {%8,%9}, {z,z,z,z};\n\t}"
        : "=f"(d[0]), "=f"(d[1]), "=f"(d[2]), "=f"(d[3])
        : "r"(a[0]), "r"(a[1]), "r"(a[2]), "r"(a[3]), "r"(b[0]), "r"(b[1]));
}

// ---- packed f32x2 ----
DINL unsigned long long splat2(float a) {
    unsigned long long r;
    asm("mov.b64 %0, {%1, %1};" : "=l"(r) : "f"(a));
    return r;
}
DINL unsigned long long mul2(unsigned long long a, unsigned long long b) {
    unsigned long long r;
    asm("mul.rn.f32x2 %0, %1, %2;" : "=l"(r) : "l"(a), "l"(b));
    return r;
}
DINL void fma2(unsigned long long& d, unsigned long long c, float x, float y) {
    asm("{\n\t.reg .b64 B;\n\tmov.b64 B, {%2, %3};\n\t"
        "fma.rn.f32x2 %0, %1, B, %0;\n\t}"
        : "+l"(d) : "l"(c), "f"(x), "f"(y));
}
DINL void unpack2(unsigned long long v, float& lo, float& hi) {
    asm("mov.b64 {%0, %1}, %2;" : "=f"(lo), "=f"(hi) : "l"(v));
}

#define SW128B(off) ((off) ^ (((off) >> 3) & 0x70))

// ============================================================================
// Kernel 1: blockwise fp8 quant of activations along K (one warp per block)
// ============================================================================
__global__ void __launch_bounds__(256)
quant_rows_kernel(const float* __restrict__ x, int K,
                  uint8_t* __restrict__ xq, float* __restrict__ sx, int Mtot) {
    int gw = blockIdx.x * 8 + (threadIdx.x >> 5);
    int lane = threadIdx.x & 31;
    int KB = K / 128;
    int m = gw / KB, kb = gw % KB;
    if (m >= Mtot) return;
    const float4 v = *(const float4*)(x + (size_t)m * K + kb * 128 + lane * 4);
    float mx = fmaxf(fmaxf(fabsf(v.x), fabsf(v.y)), fmaxf(fabsf(v.z), fabsf(v.w)));
    #pragma unroll
    for (int o = 16; o; o >>= 1) mx = fmaxf(mx, __shfl_xor_sync(0xffffffffu, mx, o));
    float scale = __fdiv_rn(fmaxf(mx, 1e-12f), 448.0f);
    uint16_t lo = cvt2_e4m3(__fdiv_rn(v.x, scale), __fdiv_rn(v.y, scale));
    uint16_t hi = cvt2_e4m3(__fdiv_rn(v.z, scale), __fdiv_rn(v.w, scale));
    *(uint32_t*)(xq + (size_t)m * K + kb * 128 + lane * 4) =
        (uint32_t)lo | ((uint32_t)hi << 16);
    if (lane == 0) sx[(size_t)kb * Mtot + m] = scale;
}

// ============================================================================
// Kernel 2: blockwise fp8 quant of weights along K (axis 0) + transpose.
//   W [K, N] f32 -> wq [n][k] bytes, sw [kb][n]
// ============================================================================
static constexpr int QW_WF   = 0;                       // float [128][132]
static constexpr int QW_PM   = 128 * 132 * 4;           // float [2][128]
static constexpr int QW_SCL  = QW_PM + 256 * 4;         // float [128]
static constexpr int QW_BT   = QW_SCL + 128 * 4;        // u32   [128][33]
static constexpr int QW_SMEM = QW_BT + 128 * 33 * 4;    // 86016

__global__ void __launch_bounds__(256)
quant_wt_kernel(const float* __restrict__ w, int K, int N,
                uint8_t* __restrict__ wq, float* __restrict__ sw) {
    extern __shared__ __align__(16) uint8_t qsm[];
    float* wf  = (float*)(qsm + QW_WF);
    float* pm  = (float*)(qsm + QW_PM);
    float* scl = (float*)(qsm + QW_SCL);
    uint32_t* bt = (uint32_t*)(qsm + QW_BT);
    const int kb = blockIdx.y, n0 = blockIdx.x * 128;
    const int tid = threadIdx.x;
    const float* src = w + (size_t)(kb * 128) * N + n0;

    #pragma unroll
    for (int i = 0; i < 16; i++) {
        int ch = i * 256 + tid;
        int k = ch >> 5, nc = ch & 31;
        cp16(smem_u32(wf + k * 132 + nc * 4), src + (size_t)k * N + nc * 4);
    }
    CP_COMMIT();
    CP_WAIT0();
    __syncthreads();

    const int c = tid & 127, h = tid >> 7;
    float mx = 0.f;
    for (int k = h * 64; k < h * 64 + 64; k++)
        mx = fmaxf(mx, fabsf(wf[k * 132 + c]));
    pm[h * 128 + c] = mx;
    __syncthreads();
    if (tid < 128) {
        float s = __fdiv_rn(fmaxf(fmaxf(pm[tid], pm[128 + tid]), 1e-12f), 448.0f);
        scl[tid] = s;
        sw[(size_t)kb * N + n0 + tid] = s;
    }
    __syncthreads();
    float s = scl[c];
    uint8_t* btb = (uint8_t*)bt;
    for (int k = h * 64; k < h * 64 + 64; k++)
        btb[c * 132 + k] = (uint8_t)cvt2_e4m3(__fdiv_rn(wf[k * 132 + c], s), 0.f);
    __syncthreads();
    #pragma unroll
    for (int i = 0; i < 16; i++) {
        int idx = i * 256 + tid;
        int r = idx >> 5, wd = idx & 31;
        ((uint32_t*)(wq + (size_t)(n0 + r) * K + (size_t)kb * 128))[wd] = bt[r * 33 + wd];
    }
}

// ============================================================================
// GEMM: BM x BN tile, 256 threads (warp grid (BM/32) x (BN/32), 32x32/warp),
// mma.sync fp8, 3-stage cp.async pipeline, ONE __syncthreads per K-block,
// scales staged via cp.async, 2 CTAs/SM.
// EPI=0 (BM=128,BN=64): out_f = C + bias.
// EPI=1 (BM=64,BN=128): h=gelu(C+bias) -> fp8 quant out_q/out_s.
// ============================================================================
static constexpr int NSTAGE = 3;
static constexpr int STAGE = 25600;            // A BM*128 | B BN*128 | sA | sB
static constexpr int SM_HDR = 1024;            // [64..576) bias
static constexpr int SMEM_GEMM = SM_HDR + NSTAGE * STAGE;   // 77824

template <int EPI>
__global__ void __launch_bounds__(256, 2)
gemm_kernel(const uint8_t* __restrict__ Aq, const float* __restrict__ sA,
            const uint8_t* __restrict__ Bq, const float* __restrict__ sB,
            const float* __restrict__ bias, int K, int N,
            float* __restrict__ out_f,
            uint8_t* __restrict__ out_q, float* __restrict__ out_s) {
    constexpr int BM = EPI ? 64 : 128;
    constexpr int BN = EPI ? 128 : 64;
    constexpr int WM = BM / 32;                 // warps along M
    constexpr int SM_B  = BM * 128;
    constexpr int SM_SA = (BM + BN) * 128;
    constexpr int SM_SB = SM_SA + BM * 4;

    extern __shared__ __align__(1024) uint8_t smem[];
    const uint32_t sbase = smem_u32(smem);
    const int tid = threadIdx.x;
    const int wid = tid >> 5, lane = tid & 31;
    const int wm = wid % WM, wn = wid / WM;
    const int g = lane >> 2, tig = lane & 3;
    const int n0 = blockIdx.x * BN, m0 = blockIdx.y * BM;
    const int NKB = K / 128;

    if (tid < BN) *(float*)(smem + 64 + tid * 4) = bias[n0 + tid];

    unsigned long long accp[2][4][2];
    #pragma unroll
    for (int mt = 0; mt < 2; mt++)
        #pragma unroll
        for (int nt = 0; nt < 4; nt++)
            #pragma unroll
            for (int p = 0; p < 2; p++) accp[mt][nt][p] = 0ull;

    // ---- pointer-increment prefetch state ----
    const int prow = tid >> 3, pcol = tid & 7;   // rows prow + 32*i
    const uint8_t* pA = Aq + (size_t)(m0 + prow) * K + pcol * 16;
    const uint8_t* pB = Bq + (size_t)(n0 + prow) * K + pcol * 16;
    const float* psAg = sA + m0 + tid * 4;             // tid < BM/4
    const float* psBg = sB + n0 + (tid - 128) * 4;     // 128 <= tid < 128+BN/4
    uint32_t swA[BM / 32], swB[BN / 32];
    #pragma unroll
    for (int i = 0; i < BM / 32; i++)
        swA[i] = SW128B((uint32_t)((prow + 32 * i) * 128 + pcol * 16));
    #pragma unroll
    for (int i = 0; i < BN / 32; i++)
        swB[i] = SW128B((uint32_t)((prow + 32 * i) * 128 + pcol * 16));

    auto prefetch = [&](int stg) {
        uint32_t st = sbase + SM_HDR + stg * STAGE;
        #pragma unroll
        for (int i = 0; i < BM / 32; i++)
            cp16(st + swA[i], pA + (size_t)(32 * i) * K);
        #pragma unroll
        for (int i = 0; i < BN / 32; i++)
            cp16(st + SM_B + swB[i], pB + (size_t)(32 * i) * K);
        if (tid < BM / 4)
            cp16(st + SM_SA + tid * 16, psAg);
        else if (tid >= 128 && tid < 128 + BN / 4)
            cp16(st + SM_SB + (tid - 128) * 16, psBg);
        pA += 128; pB += 128; psAg += MROWS; psBg += N;
    };

    prefetch(0); CP_COMMIT();
    prefetch(1); CP_COMMIT();

    // ---- hoisted ldmatrix addressing (stage-relative offsets) ----
    const int a_q = lane >> 3;
    const int rl  = lane & 7;
    uint32_t rowA[2], xcolA[4], rowB[2], xcolB[4];
    #pragma unroll
    for (int mt = 0; mt < 2; mt++)
        rowA[mt] = (uint32_t)((wm * 32 + mt * 16 + (a_q & 1) * 8 + rl) * 128);
    #pragma unroll
    for (int ks = 0; ks < 4; ks++)
        xcolA[ks] = (uint32_t)((ks * 32 + (a_q >> 1) * 16) ^ (rl << 4));
    // B pairs: x4 load np covers n-rows [np*16, np*16+16) of the warp block
    #pragma unroll
    for (int np = 0; np < 2; np++)
        rowB[np] = (uint32_t)((wn * 32 + np * 16 + ((lane >> 4) & 1) * 8 + rl) * 128);
    #pragma unroll
    for (int ks = 0; ks < 4; ks++)
        xcolB[ks] = (uint32_t)((ks * 32 + ((lane >> 3) & 1) * 16) ^ (rl << 4));

    int sidx = 0;   // stage holding current kb
    for (int kb = 0; kb < NKB; kb++) {
        const uint32_t stA = sbase + SM_HDR + sidx * STAGE;
        const uint32_t stB = stA + SM_B;

        CP_WAIT1();          // stage kb landed (group kb+1 may still be in flight)
        __syncthreads();     // all warps see stage kb; implies all finished kb-1

        // prefetch kb+2 into slot (kb+2)%3 == slot (kb-1)%3 — free after the sync
        int sidx2 = sidx + 2 >= NSTAGE ? sidx + 2 - NSTAGE : sidx + 2;
        if (kb + 2 < NKB) prefetch(sidx2);
        CP_COMMIT();         // unconditional: uniform wait_group accounting

        float D[2][4][4];
        #pragma unroll
        for (int ks = 0; ks < 4; ks++) {
            uint32_t af[2][4], bq[2][4];
            #pragma unroll
            for (int mt = 0; mt < 2; mt++) ldsm_x4(af[mt], stA + rowA[mt] + xcolA[ks]);
            #pragma unroll
            for (int np = 0; np < 2; np++) ldsm_x4(bq[np], stB + rowB[np] + xcolB[ks]);
            #pragma unroll
            for (int mt = 0; mt < 2; mt++)
                #pragma unroll
                for (int nt = 0; nt < 4; nt++) {
                    const uint32_t* bf = &bq[nt >> 1][(nt & 1) * 2];
                    if (ks == 0) mma_fp8_zc(D[mt][nt], af[mt], bf);
                    else         mma_fp8   (D[mt][nt], af[mt], bf);
                }
        }

        // fine-grained scale promotion (packed f32x2): acc += (sa*sb) * D
        const uint8_t* sAs = smem + SM_HDR + sidx * STAGE + SM_SA;
        const uint8_t* sBs = smem + SM_HDR + sidx * STAGE + SM_SB;
        unsigned long long SB2[4], saS[2][2];
        #pragma unroll
        for (int nt = 0; nt < 4; nt++)
            SB2[nt] = *(const unsigned long long*)(sBs + (wn * 32 + nt * 8 + tig * 2) * 4);
        #pragma unroll
        for (int mt = 0; mt < 2; mt++)
            #pragma unroll
            for (int j = 0; j < 2; j++)
                saS[mt][j] = splat2(*(const float*)(sAs + (wm * 32 + mt * 16 + j * 8 + g) * 4));
        #pragma unroll
        for (int mt = 0; mt < 2; mt++)
            #pragma unroll
            for (int nt = 0; nt < 4; nt++) {
                unsigned long long c01 = mul2(saS[mt][0], SB2[nt]);
                unsigned long long c23 = mul2(saS[mt][1], SB2[nt]);
                fma2(accp[mt][nt][0], c01, D[mt][nt][0], D[mt][nt][1]);
                fma2(accp[mt][nt][1], c23, D[mt][nt][2], D[mt][nt][3]);
            }

        sidx = sidx + 1 >= NSTAGE ? 0 : sidx + 1;
    }
    __syncthreads();   // mainloop smem dead; epilogue reuses it

    // ------------------------- epilogue -------------------------
    constexpr int FBS = BM + 1;                 // fb stride ([col][row])
    float* fb = (float*)(smem + SM_HDR);
    const float* biasS = (const float*)(smem + 64);
    #pragma unroll
    for (int mt = 0; mt < 2; mt++)
        #pragma unroll
        for (int nt = 0; nt < 4; nt++)
            #pragma unroll
            for (int p = 0; p < 2; p++) {
                float lo, hi;
                unpack2(accp[mt][nt][p], lo, hi);
                int row = wm * 32 + mt * 16 + p * 8 + g;
                int c0 = wn * 32 + nt * 8 + tig * 2;
                #pragma unroll
                for (int e = 0; e < 2; e++) {
                    int col = c0 + e;
                    float u = (e ? hi : lo) + biasS[col];
                    float v;
                    if (EPI == 1) {
                        float t = 0.7978845608028654f * (u + 0.044715f * u * u * u);
                        v = 0.5f * u * (1.0f + tanhf(t));
                    } else {
                        v = u;
                    }
                    fb[col * FBS + row] = v;
                }
            }
    __syncthreads();

    if (EPI == 0) {
        // BM=128, BN=64: write 8192 floats, 32 per thread
        #pragma unroll
        for (int i = 0; i < 32; i++) {
            int idx = i * 256 + tid;
            int r = idx >> 6, c = idx & 63;
            out_f[(size_t)(m0 + r) * N + n0 + c] = fb[c * FBS + r];
        }
    } else {
        // BM=64, BN=128: blockwise re-quant of h along the 128 cols
        uint32_t* bt = (uint32_t*)(smem + SM_HDR + 128 * FBS * 4);     // [64][33]
        float* pm = (float*)((uint8_t*)bt + 64 * 33 * 4);              // [4][64]+[64]
        const int r = tid & 63, q = tid >> 6;        // 4 col-segments of 32
        float mx = 0.f;
        #pragma unroll
        for (int c = q * 32; c < q * 32 + 32; c++) mx = fmaxf(mx, fabsf(fb[c * FBS + r]));
        pm[q * 64 + r] = mx;
        __syncthreads();
        if (tid < 64) {
            float m01 = fmaxf(pm[tid], pm[64 + tid]);
            float m23 = fmaxf(pm[128 + tid], pm[192 + tid]);
            float sc = __fdiv_rn(fmaxf(fmaxf(m01, m23), 1e-12f), 448.0f);
            pm[256 + tid] = sc;
            out_s[(size_t)(n0 >> 7) * MROWS + m0 + tid] = sc;
        }
        __syncthreads();
        float sc = pm[256 + r];
        #pragma unroll
        for (int c = q * 32; c < q * 32 + 32; c += 4) {
            uint16_t lo = cvt2_e4m3(__fdiv_rn(fb[(c + 0) * FBS + r], sc),
                                    __fdiv_rn(fb[(c + 1) * FBS + r], sc));
            uint16_t hi = cvt2_e4m3(__fdiv_rn(fb[(c + 2) * FBS + r], sc),
                                    __fdiv_rn(fb[(c + 3) * FBS + r], sc));
            bt[r * 33 + (c >> 2)] = (uint32_t)lo | ((uint32_t)hi << 16);
        }
        __syncthreads();
        // store 64 rows x 32 words, 8 per thread
        #pragma unroll
        for (int i = 0; i < 8; i++) {
            int idx = i * 256 + tid;
            int rr = idx >> 5, wd = idx & 31;
            ((uint32_t*)(out_q + (size_t)(m0 + rr) * N + n0))[wd] = bt[rr * 33 + wd];
        }
    }
}

// ============================================================================
// Launch
// ============================================================================
extern "C" void kernel_launch(void* const* d_in, const int* in_sizes, int n_in,
                              void* d_out, int out_size) {
    const float* x  = (const float*)d_in[0];
    const float* w1 = (const float*)d_in[1];
    const float* b1 = (const float*)d_in[2];
    const float* w2 = (const float*)d_in[3];
    const float* b2 = (const float*)d_in[4];
    float* out = (float*)d_out;

    cudaFuncSetAttribute(gemm_kernel<0>, cudaFuncAttributeMaxDynamicSharedMemorySize, SMEM_GEMM);
    cudaFuncSetAttribute(gemm_kernel<1>, cudaFuncAttributeMaxDynamicSharedMemorySize, SMEM_GEMM);
    cudaFuncSetAttribute(quant_wt_kernel, cudaFuncAttributeMaxDynamicSharedMemorySize, QW_SMEM);

    uint8_t *xq, *w1q, *w2q, *hq;
    float *sx, *sw1, *sw2, *sh;
    cudaGetSymbolAddress((void**)&xq,  g_xq);
    cudaGetSymbolAddress((void**)&sx,  g_sx);
    cudaGetSymbolAddress((void**)&w1q, g_w1q);
    cudaGetSymbolAddress((void**)&sw1, g_sw1);
    cudaGetSymbolAddress((void**)&w2q, g_w2q);
    cudaGetSymbolAddress((void**)&sw2, g_sw2);
    cudaGetSymbolAddress((void**)&hq,  g_hq);
    cudaGetSymbolAddress((void**)&sh,  g_sh);

    // 1) quantize activations x
    quant_rows_kernel<<<(MROWS * (K1 / 128)) / 8, 256>>>(x, K1, xq, sx, MROWS);

    // 2) quantize + transpose weights (smem-staged single read)
    quant_wt_kernel<<<dim3(N1 / 128, K1 / 128), 256, QW_SMEM>>>(w1, K1, N1, w1q, sw1);
    quant_wt_kernel<<<dim3(N2 / 128, K2 / 128), 256, QW_SMEM>>>(w2, K2, N2, w2q, sw2);

    // 3) GEMM1 (64x128 tiles) + bias + GELU + fused re-quant of h
    gemm_kernel<1><<<dim3(N1 / 128, MROWS / 64), 256, SMEM_GEMM>>>(
        xq, sx, w1q, sw1, b1, K1, N1, nullptr, hq, sh);

    // 4) GEMM2 (128x64 tiles) + bias -> out
    gemm_kernel<0><<<dim3(N2 / 64, MROWS / 128), 256, SMEM_GEMM>>>(
        hq, sh, w2q, sw2, b2, K2, N2, out, nullptr, nullptr);
}

// round 11
// speedup vs baseline: 1.2188x; 1.0575x over previous
#include <cuda_runtime.h>
#include <cstdint>

// ============================================================================
// Problem shapes:
//  x [8192,2048] f32 ; W1 [2048,8192] ; b1 [8192] ; W2 [8192,8192] ; b2 [8192]
//  out = fp8fakequant_gemm(gelu_tanh(fp8fakequant_gemm(x,W1)+b1), W2) + b2
//
// Math: blockwise fp8 fake-quant factors exactly:
//   C[m,n] = sum_kb sA[kb][m]*sB[kb][n] * ( sum_{k in kb} qA[m,k]*qB[n,k] )
// Inner sums on fp8 tensor cores (mma.sync m16n8k32 e4m3, fp32 accum);
// scale promotion in CUDA-core fp32 (packed f32x2).
// R11: instruction-diet on R10 skeleton — RZ-based zero-C MMA, precombined
//      ldmatrix offsets, prefetch issued under ks=0 MMA shadow.
// ============================================================================
static constexpr int MROWS = 8192;
static constexpr int K1 = 2048, N1 = 8192;
static constexpr int K2 = 8192, N2 = 8192;

// ---------------------------------------------------------------------------
// Scratch (device globals; runtime allocation forbidden)
// ---------------------------------------------------------------------------
__device__ __align__(256) uint8_t g_xq [(size_t)MROWS * K1];      // [m][k]
__device__ __align__(256) float   g_sx [(K1 / 128) * MROWS];      // [kb][m]
__device__ __align__(256) uint8_t g_w1q[(size_t)N1 * K1];         // [n][k]
__device__ __align__(256) float   g_sw1[(K1 / 128) * N1];         // [kb][n]
__device__ __align__(256) uint8_t g_hq [(size_t)MROWS * N1];      // [m][k]
__device__ __align__(256) float   g_sh [(N1 / 128) * MROWS];      // [kb][m]
__device__ __align__(256) uint8_t g_w2q[(size_t)N2 * K2];         // [n][k]
__device__ __align__(256) float   g_sw2[(K2 / 128) * N2];         // [kb][n]

#define DINL __device__ __forceinline__

// ---------------------------------------------------------------------------
// Base-ISA PTX helpers
// ---------------------------------------------------------------------------
DINL uint32_t smem_u32(const void* p) {
    uint32_t a;
    asm("{ .reg .u64 t; cvta.to.shared.u64 t, %1; cvt.u32.u64 %0, t; }"
        : "=r"(a) : "l"(p));
    return a;
}

DINL void cp16(uint32_t dst, const void* src) {
    asm volatile("cp.async.cg.shared.global [%0], [%1], 16;"
                 :: "r"(dst), "l"(src) : "memory");
}
#define CP_COMMIT() asm volatile("cp.async.commit_group;" ::: "memory")
#define CP_WAIT1()  asm volatile("cp.async.wait_group 1;" ::: "memory")
#define CP_WAIT0()  asm volatile("cp.async.wait_group 0;" ::: "memory")

// e4m3x2 pack: low byte = a, high byte = b (RNE, saturate to +-448)
DINL uint16_t cvt2_e4m3(float a, float b) {
    uint16_t r;
    asm("cvt.rn.satfinite.e4m3x2.f32 %0, %1, %2;" : "=h"(r) : "f"(b), "f"(a));
    return r;
}

DINL void ldsm_x4(uint32_t* r, uint32_t addr) {
    asm volatile("ldmatrix.sync.aligned.m8n8.x4.shared.b16 {%0,%1,%2,%3}, [%4];"
        : "=r"(r[0]), "=r"(r[1]), "=r"(r[2]), "=r"(r[3]) : "r"(addr));
}

// fp8 warp MMA (base ISA): D(16x8,f32) += A(16x32,e4m3) * B(32x8,e4m3)
DINL void mma_fp8(float* d, const uint32_t* a, const uint32_t* b) {
    asm volatile(
        "mma.sync.aligned.m16n8k32.row.col.f32.e4m3.e4m3.f32 "
        "{%0,%1,%2,%3}, {%4,%5,%6,%7}, {%8,%9}, {%0,%1,%2,%3};"
        : "+f"(d[0]), "+f"(d[1]), "+f"(d[2]), "+f"(d[3])
        : "r"(a[0]), "r"(a[1]), "r"(a[2]), "r"(a[3]), "r"(b[0]), "r"(b[1]));
}
// zero-C variant: D = A*B; zeros passed as operands so ptxas can use RZ
DINL void mma_fp8_zc(float* d, const uint32_t* a, const uint32_t* b) {
    asm volatile(
        "mma.sync.aligned.m16n8k32.row.col.f32.e4m3.e4m3.f32 "
        "{%0,%1,%2,%3}, {%4,%5,%6,%7}, {%8,%9}, {%10,%11,%12,%13};"
        : "=f"(d[0]), "=f"(d[1]), "=f"(d[2]), "=f"(d[3])
        : "r"(a[0]), "r"(a[1]), "r"(a[2]), "r"(a[3]), "r"(b[0]), "r"(b[1]),
          "f"(0.0f), "f"(0.0f), "f"(0.0f), "f"(0.0f));
}

// ---- packed f32x2 ----
DINL unsigned long long splat2(float a) {
    unsigned long long r;
    asm("mov.b64 %0, {%1, %1};" : "=l"(r) : "f"(a));
    return r;
}
DINL unsigned long long mul2(unsigned long long a, unsigned long long b) {
    unsigned long long r;
    asm("mul.rn.f32x2 %0, %1, %2;" : "=l"(r) : "l"(a), "l"(b));
    return r;
}
DINL void fma2(unsigned long long& d, unsigned long long c, float x, float y) {
    asm("{\n\t.reg .b64 B;\n\tmov.b64 B, {%2, %3};\n\t"
        "fma.rn.f32x2 %0, %1, B, %0;\n\t}"
        : "+l"(d) : "l"(c), "f"(x), "f"(y));
}
DINL void unpack2(unsigned long long v, float& lo, float& hi) {
    asm("mov.b64 {%0, %1}, %2;" : "=f"(lo), "=f"(hi) : "l"(v));
}

#define SW128B(off) ((off) ^ (((off) >> 3) & 0x70))

// ============================================================================
// Kernel 1: blockwise fp8 quant of activations along K (one warp per block)
// ============================================================================
__global__ void __launch_bounds__(256)
quant_rows_kernel(const float* __restrict__ x, int K,
                  uint8_t* __restrict__ xq, float* __restrict__ sx, int Mtot) {
    int gw = blockIdx.x * 8 + (threadIdx.x >> 5);
    int lane = threadIdx.x & 31;
    int KB = K / 128;
    int m = gw / KB, kb = gw % KB;
    if (m >= Mtot) return;
    const float4 v = *(const float4*)(x + (size_t)m * K + kb * 128 + lane * 4);
    float mx = fmaxf(fmaxf(fabsf(v.x), fabsf(v.y)), fmaxf(fabsf(v.z), fabsf(v.w)));
    #pragma unroll
    for (int o = 16; o; o >>= 1) mx = fmaxf(mx, __shfl_xor_sync(0xffffffffu, mx, o));
    float scale = __fdiv_rn(fmaxf(mx, 1e-12f), 448.0f);
    uint16_t lo = cvt2_e4m3(__fdiv_rn(v.x, scale), __fdiv_rn(v.y, scale));
    uint16_t hi = cvt2_e4m3(__fdiv_rn(v.z, scale), __fdiv_rn(v.w, scale));
    *(uint32_t*)(xq + (size_t)m * K + kb * 128 + lane * 4) =
        (uint32_t)lo | ((uint32_t)hi << 16);
    if (lane == 0) sx[(size_t)kb * Mtot + m] = scale;
}

// ============================================================================
// Kernel 2: blockwise fp8 quant of weights along K (axis 0) + transpose.
//   W [K, N] f32 -> wq [n][k] bytes, sw [kb][n]
// ============================================================================
static constexpr int QW_WF   = 0;                       // float [128][132]
static constexpr int QW_PM   = 128 * 132 * 4;           // float [2][128]
static constexpr int QW_SCL  = QW_PM + 256 * 4;         // float [128]
static constexpr int QW_BT   = QW_SCL + 128 * 4;        // u32   [128][33]
static constexpr int QW_SMEM = QW_BT + 128 * 33 * 4;    // 86016

__global__ void __launch_bounds__(256)
quant_wt_kernel(const float* __restrict__ w, int K, int N,
                uint8_t* __restrict__ wq, float* __restrict__ sw) {
    extern __shared__ __align__(16) uint8_t qsm[];
    float* wf  = (float*)(qsm + QW_WF);
    float* pm  = (float*)(qsm + QW_PM);
    float* scl = (float*)(qsm + QW_SCL);
    uint32_t* bt = (uint32_t*)(qsm + QW_BT);
    const int kb = blockIdx.y, n0 = blockIdx.x * 128;
    const int tid = threadIdx.x;
    const float* src = w + (size_t)(kb * 128) * N + n0;

    #pragma unroll
    for (int i = 0; i < 16; i++) {
        int ch = i * 256 + tid;
        int k = ch >> 5, nc = ch & 31;
        cp16(smem_u32(wf + k * 132 + nc * 4), src + (size_t)k * N + nc * 4);
    }
    CP_COMMIT();
    CP_WAIT0();
    __syncthreads();

    const int c = tid & 127, h = tid >> 7;
    float mx = 0.f;
    for (int k = h * 64; k < h * 64 + 64; k++)
        mx = fmaxf(mx, fabsf(wf[k * 132 + c]));
    pm[h * 128 + c] = mx;
    __syncthreads();
    if (tid < 128) {
        float s = __fdiv_rn(fmaxf(fmaxf(pm[tid], pm[128 + tid]), 1e-12f), 448.0f);
        scl[tid] = s;
        sw[(size_t)kb * N + n0 + tid] = s;
    }
    __syncthreads();
    float s = scl[c];
    uint8_t* btb = (uint8_t*)bt;
    for (int k = h * 64; k < h * 64 + 64; k++)
        btb[c * 132 + k] = (uint8_t)cvt2_e4m3(__fdiv_rn(wf[k * 132 + c], s), 0.f);
    __syncthreads();
    #pragma unroll
    for (int i = 0; i < 16; i++) {
        int idx = i * 256 + tid;
        int r = idx >> 5, wd = idx & 31;
        ((uint32_t*)(wq + (size_t)(n0 + r) * K + (size_t)kb * 128))[wd] = bt[r * 33 + wd];
    }
}

// ============================================================================
// GEMM: BM x BN tile, 256 threads (warp grid (BM/32) x (BN/32), 32x32/warp),
// mma.sync fp8, 3-stage cp.async pipeline, ONE __syncthreads per K-block,
// scales staged via cp.async, 2 CTAs/SM, prefetch under ks=0 MMA shadow.
// EPI=0 (BM=128,BN=64): out_f = C + bias.
// EPI=1 (BM=64,BN=128): h=gelu(C+bias) -> fp8 quant out_q/out_s.
// ============================================================================
static constexpr int NSTAGE = 3;
static constexpr int STAGE = 25600;            // A BM*128 | B BN*128 | sA | sB
static constexpr int SM_HDR = 1024;            // [64..576) bias
static constexpr int SMEM_GEMM = SM_HDR + NSTAGE * STAGE;   // 77824

template <int EPI>
__global__ void __launch_bounds__(256, 2)
gemm_kernel(const uint8_t* __restrict__ Aq, const float* __restrict__ sA,
            const uint8_t* __restrict__ Bq, const float* __restrict__ sB,
            const float* __restrict__ bias, int K, int N,
            float* __restrict__ out_f,
            uint8_t* __restrict__ out_q, float* __restrict__ out_s) {
    constexpr int BM = EPI ? 64 : 128;
    constexpr int BN = EPI ? 128 : 64;
    constexpr int WM = BM / 32;                 // warps along M
    constexpr int SM_B  = BM * 128;
    constexpr int SM_SA = (BM + BN) * 128;
    constexpr int SM_SB = SM_SA + BM * 4;

    extern __shared__ __align__(1024) uint8_t smem[];
    const uint32_t sbase = smem_u32(smem);
    const int tid = threadIdx.x;
    const int wid = tid >> 5, lane = tid & 31;
    const int wm = wid % WM, wn = wid / WM;
    const int g = lane >> 2, tig = lane & 3;
    const int n0 = blockIdx.x * BN, m0 = blockIdx.y * BM;
    const int NKB = K / 128;

    if (tid < BN) *(float*)(smem + 64 + tid * 4) = bias[n0 + tid];

    unsigned long long accp[2][4][2];
    #pragma unroll
    for (int mt = 0; mt < 2; mt++)
        #pragma unroll
        for (int nt = 0; nt < 4; nt++)
            #pragma unroll
            for (int p = 0; p < 2; p++) accp[mt][nt][p] = 0ull;

    // ---- pointer-increment prefetch state ----
    const int prow = tid >> 3, pcol = tid & 7;   // rows prow + 32*i
    const uint8_t* pA = Aq + (size_t)(m0 + prow) * K + pcol * 16;
    const uint8_t* pB = Bq + (size_t)(n0 + prow) * K + pcol * 16;
    const float* psAg = sA + m0 + tid * 4;             // tid < BM/4
    const float* psBg = sB + n0 + (tid - 128) * 4;     // 128 <= tid < 128+BN/4
    uint32_t swA[BM / 32], swB[BN / 32];
    #pragma unroll
    for (int i = 0; i < BM / 32; i++)
        swA[i] = SW128B((uint32_t)((prow + 32 * i) * 128 + pcol * 16));
    #pragma unroll
    for (int i = 0; i < BN / 32; i++)
        swB[i] = SW128B((uint32_t)((prow + 32 * i) * 128 + pcol * 16));

    auto prefetch = [&](int stg) {
        uint32_t st = sbase + SM_HDR + stg * STAGE;
        #pragma unroll
        for (int i = 0; i < BM / 32; i++)
            cp16(st + swA[i], pA + (size_t)(32 * i) * K);
        #pragma unroll
        for (int i = 0; i < BN / 32; i++)
            cp16(st + SM_B + swB[i], pB + (size_t)(32 * i) * K);
        if (tid < BM / 4)
            cp16(st + SM_SA + tid * 16, psAg);
        else if (tid >= 128 && tid < 128 + BN / 4)
            cp16(st + SM_SB + (tid - 128) * 16, psBg);
        pA += 128; pB += 128; psAg += MROWS; psBg += N;
    };

    prefetch(0); CP_COMMIT();
    prefetch(1); CP_COMMIT();

    // ---- precombined ldmatrix offsets (stage-relative, row+swizzled-col) ----
    const int a_q = lane >> 3;
    const int rl  = lane & 7;
    uint32_t offA[2][4], offB[2][4];
    #pragma unroll
    for (int mt = 0; mt < 2; mt++) {
        uint32_t rowA = (uint32_t)((wm * 32 + mt * 16 + (a_q & 1) * 8 + rl) * 128);
        #pragma unroll
        for (int ks = 0; ks < 4; ks++)
            offA[mt][ks] = rowA + (uint32_t)((ks * 32 + (a_q >> 1) * 16) ^ (rl << 4));
    }
    // B pairs: x4 load np covers n-rows [np*16, np*16+16) of the warp block
    #pragma unroll
    for (int np = 0; np < 2; np++) {
        uint32_t rowB = (uint32_t)((wn * 32 + np * 16 + ((lane >> 4) & 1) * 8 + rl) * 128);
        #pragma unroll
        for (int ks = 0; ks < 4; ks++)
            offB[np][ks] = rowB + (uint32_t)((ks * 32 + ((lane >> 3) & 1) * 16) ^ (rl << 4));
    }

    int sidx = 0;   // stage holding current kb
    for (int kb = 0; kb < NKB; kb++) {
        const uint32_t stA = sbase + SM_HDR + sidx * STAGE;
        const uint32_t stB = stA + SM_B;

        CP_WAIT1();          // stage kb landed (group kb+1 may still be in flight)
        __syncthreads();     // all warps see stage kb; implies all finished kb-1

        float D[2][4][4];
        // ---- ks = 0: fragments + MMAs first, then prefetch under their shadow
        {
            uint32_t af[2][4], bq[2][4];
            #pragma unroll
            for (int mt = 0; mt < 2; mt++) ldsm_x4(af[mt], stA + offA[mt][0]);
            #pragma unroll
            for (int np = 0; np < 2; np++) ldsm_x4(bq[np], stB + offB[np][0]);
            #pragma unroll
            for (int mt = 0; mt < 2; mt++)
                #pragma unroll
                for (int nt = 0; nt < 4; nt++)
                    mma_fp8_zc(D[mt][nt], af[mt], &bq[nt >> 1][(nt & 1) * 2]);

            // prefetch kb+2 into slot (kb+2)%3 == (kb-1)%3 — free after the sync
            int sidx2 = sidx + 2 >= NSTAGE ? sidx + 2 - NSTAGE : sidx + 2;
            if (kb + 2 < NKB) prefetch(sidx2);
            CP_COMMIT();     // unconditional: uniform wait_group accounting
        }
        // ---- ks = 1..3
        #pragma unroll
        for (int ks = 1; ks < 4; ks++) {
            uint32_t af[2][4], bq[2][4];
            #pragma unroll
            for (int mt = 0; mt < 2; mt++) ldsm_x4(af[mt], stA + offA[mt][ks]);
            #pragma unroll
            for (int np = 0; np < 2; np++) ldsm_x4(bq[np], stB + offB[np][ks]);
            #pragma unroll
            for (int mt = 0; mt < 2; mt++)
                #pragma unroll
                for (int nt = 0; nt < 4; nt++)
                    mma_fp8(D[mt][nt], af[mt], &bq[nt >> 1][(nt & 1) * 2]);
        }

        // fine-grained scale promotion (packed f32x2): acc += (sa*sb) * D
        const uint8_t* sAs = smem + SM_HDR + sidx * STAGE + SM_SA;
        const uint8_t* sBs = smem + SM_HDR + sidx * STAGE + SM_SB;
        unsigned long long SB2[4], saS[2][2];
        #pragma unroll
        for (int nt = 0; nt < 4; nt++)
            SB2[nt] = *(const unsigned long long*)(sBs + (wn * 32 + nt * 8 + tig * 2) * 4);
        #pragma unroll
        for (int mt = 0; mt < 2; mt++)
            #pragma unroll
            for (int j = 0; j < 2; j++)
                saS[mt][j] = splat2(*(const float*)(sAs + (wm * 32 + mt * 16 + j * 8 + g) * 4));
        #pragma unroll
        for (int mt = 0; mt < 2; mt++)
            #pragma unroll
            for (int nt = 0; nt < 4; nt++) {
                unsigned long long c01 = mul2(saS[mt][0], SB2[nt]);
                unsigned long long c23 = mul2(saS[mt][1], SB2[nt]);
                fma2(accp[mt][nt][0], c01, D[mt][nt][0], D[mt][nt][1]);
                fma2(accp[mt][nt][1], c23, D[mt][nt][2], D[mt][nt][3]);
            }

        sidx = sidx + 1 >= NSTAGE ? 0 : sidx + 1;
    }
    __syncthreads();   // mainloop smem dead; epilogue reuses it

    // ------------------------- epilogue -------------------------
    constexpr int FBS = BM + 1;                 // fb stride ([col][row])
    float* fb = (float*)(smem + SM_HDR);
    const float* biasS = (const float*)(smem + 64);
    #pragma unroll
    for (int mt = 0; mt < 2; mt++)
        #pragma unroll
        for (int nt = 0; nt < 4; nt++)
            #pragma unroll
            for (int p = 0; p < 2; p++) {
                float lo, hi;
                unpack2(accp[mt][nt][p], lo, hi);
                int row = wm * 32 + mt * 16 + p * 8 + g;
                int c0 = wn * 32 + nt * 8 + tig * 2;
                #pragma unroll
                for (int e = 0; e < 2; e++) {
                    int col = c0 + e;
                    float u = (e ? hi : lo) + biasS[col];
                    float v;
                    if (EPI == 1) {
                        float t = 0.7978845608028654f * (u + 0.044715f * u * u * u);
                        v = 0.5f * u * (1.0f + tanhf(t));
                    } else {
                        v = u;
                    }
                    fb[col * FBS + row] = v;
                }
            }
    __syncthreads();

    if (EPI == 0) {
        // BM=128, BN=64: write 8192 floats, 32 per thread
        #pragma unroll
        for (int i = 0; i < 32; i++) {
            int idx = i * 256 + tid;
            int r = idx >> 6, c = idx & 63;
            out_f[(size_t)(m0 + r) * N + n0 + c] = fb[c * FBS + r];
        }
    } else {
        // BM=64, BN=128: blockwise re-quant of h along the 128 cols
        uint32_t* bt = (uint32_t*)(smem + SM_HDR + 128 * FBS * 4);     // [64][33]
        float* pm = (float*)((uint8_t*)bt + 64 * 33 * 4);              // [4][64]+[64]
        const int r = tid & 63, q = tid >> 6;        // 4 col-segments of 32
        float mx = 0.f;
        #pragma unroll
        for (int c = q * 32; c < q * 32 + 32; c++) mx = fmaxf(mx, fabsf(fb[c * FBS + r]));
        pm[q * 64 + r] = mx;
        __syncthreads();
        if (tid < 64) {
            float m01 = fmaxf(pm[tid], pm[64 + tid]);
            float m23 = fmaxf(pm[128 + tid], pm[192 + tid]);
            float sc = __fdiv_rn(fmaxf(fmaxf(m01, m23), 1e-12f), 448.0f);
            pm[256 + tid] = sc;
            out_s[(size_t)(n0 >> 7) * MROWS + m0 + tid] = sc;
        }
        __syncthreads();
        float sc = pm[256 + r];
        #pragma unroll
        for (int c = q * 32; c < q * 32 + 32; c += 4) {
            uint16_t lo = cvt2_e4m3(__fdiv_rn(fb[(c + 0) * FBS + r], sc),
                                    __fdiv_rn(fb[(c + 1) * FBS + r], sc));
            uint16_t hi = cvt2_e4m3(__fdiv_rn(fb[(c + 2) * FBS + r], sc),
                                    __fdiv_rn(fb[(c + 3) * FBS + r], sc));
            bt[r * 33 + (c >> 2)] = (uint32_t)lo | ((uint32_t)hi << 16);
        }
        __syncthreads();
        // store 64 rows x 32 words, 8 per thread
        #pragma unroll
        for (int i = 0; i < 8; i++) {
            int idx = i * 256 + tid;
            int rr = idx >> 5, wd = idx & 31;
            ((uint32_t*)(out_q + (size_t)(m0 + rr) * N + n0))[wd] = bt[rr * 33 + wd];
        }
    }
}

// ============================================================================
// Launch
// ============================================================================
extern "C" void kernel_launch(void* const* d_in, const int* in_sizes, int n_in,
                              void* d_out, int out_size) {
    const float* x  = (const float*)d_in[0];
    const float* w1 = (const float*)d_in[1];
    const float* b1 = (const float*)d_in[2];
    const float* w2 = (const float*)d_in[3];
    const float* b2 = (const float*)d_in[4];
    float* out = (float*)d_out;

    cudaFuncSetAttribute(gemm_kernel<0>, cudaFuncAttributeMaxDynamicSharedMemorySize, SMEM_GEMM);
    cudaFuncSetAttribute(gemm_kernel<1>, cudaFuncAttributeMaxDynamicSharedMemorySize, SMEM_GEMM);
    cudaFuncSetAttribute(quant_wt_kernel, cudaFuncAttributeMaxDynamicSharedMemorySize, QW_SMEM);

    uint8_t *xq, *w1q, *w2q, *hq;
    float *sx, *sw1, *sw2, *sh;
    cudaGetSymbolAddress((void**)&xq,  g_xq);
    cudaGetSymbolAddress((void**)&sx,  g_sx);
    cudaGetSymbolAddress((void**)&w1q, g_w1q);
    cudaGetSymbolAddress((void**)&sw1, g_sw1);
    cudaGetSymbolAddress((void**)&w2q, g_w2q);
    cudaGetSymbolAddress((void**)&sw2, g_sw2);
    cudaGetSymbolAddress((void**)&hq,  g_hq);
    cudaGetSymbolAddress((void**)&sh,  g_sh);

    // 1) quantize activations x
    quant_rows_kernel<<<(MROWS * (K1 / 128)) / 8, 256>>>(x, K1, xq, sx, MROWS);

    // 2) quantize + transpose weights (smem-staged single read)
    quant_wt_kernel<<<dim3(N1 / 128, K1 / 128), 256, QW_SMEM>>>(w1, K1, N1, w1q, sw1);
    quant_wt_kernel<<<dim3(N2 / 128, K2 / 128), 256, QW_SMEM>>>(w2, K2, N2, w2q, sw2);

    // 3) GEMM1 (64x128 tiles) + bias + GELU + fused re-quant of h
    gemm_kernel<1><<<dim3(N1 / 128, MROWS / 64), 256, SMEM_GEMM>>>(
        xq, sx, w1q, sw1, b1, K1, N1, nullptr, hq, sh);

    // 4) GEMM2 (128x64 tiles) + bias -> out
    gemm_kernel<0><<<dim3(N2 / 64, MROWS / 128), 256, SMEM_GEMM>>>(
        hq, sh, w2q, sw2, b2, K2, N2, out, nullptr, nullptr);
}

// round 13
// speedup vs baseline: 1.2469x; 1.0231x over previous
#include <cuda_runtime.h>
#include <cstdint>

// ============================================================================
// Problem shapes:
//  x [8192,2048] f32 ; W1 [2048,8192] ; b1 [8192] ; W2 [8192,8192] ; b2 [8192]
//  out = fp8fakequant_gemm(gelu_tanh(fp8fakequant_gemm(x,W1)+b1), W2) + b2
//
// Math: blockwise fp8 fake-quant factors exactly:
//   C[m,n] = sum_kb sA[kb][m]*sB[kb][n] * ( sum_{k in kb} qA[m,k]*qB[n,k] )
// Inner sums on fp8 tensor cores (mma.sync m16n8k32 e4m3, fp32 accum);
// scale promotion in CUDA-core fp32 (packed f32x2).
// R13 == R12 with the host/device constexpr fix:
//   GEMM2 at 64x64 tiles / 128 threads / 4 CTAs per SM (finer barrier
//   domains); GEMM1 keeps 64x128 / 256 threads / 2 CTAs (re-quant fusion).
// ============================================================================
static constexpr int MROWS = 8192;
static constexpr int K1 = 2048, N1 = 8192;
static constexpr int K2 = 8192, N2 = 8192;

// ---------------------------------------------------------------------------
// Scratch (device globals; runtime allocation forbidden)
// ---------------------------------------------------------------------------
__device__ __align__(256) uint8_t g_xq [(size_t)MROWS * K1];      // [m][k]
__device__ __align__(256) float   g_sx [(K1 / 128) * MROWS];      // [kb][m]
__device__ __align__(256) uint8_t g_w1q[(size_t)N1 * K1];         // [n][k]
__device__ __align__(256) float   g_sw1[(K1 / 128) * N1];         // [kb][n]
__device__ __align__(256) uint8_t g_hq [(size_t)MROWS * N1];      // [m][k]
__device__ __align__(256) float   g_sh [(N1 / 128) * MROWS];      // [kb][m]
__device__ __align__(256) uint8_t g_w2q[(size_t)N2 * K2];         // [n][k]
__device__ __align__(256) float   g_sw2[(K2 / 128) * N2];         // [kb][n]

#define DINL __device__ __forceinline__

// ---------------------------------------------------------------------------
// Base-ISA PTX helpers
// ---------------------------------------------------------------------------
DINL uint32_t smem_u32(const void* p) {
    uint32_t a;
    asm("{ .reg .u64 t; cvta.to.shared.u64 t, %1; cvt.u32.u64 %0, t; }"
        : "=r"(a) : "l"(p));
    return a;
}

DINL void cp16(uint32_t dst, const void* src) {
    asm volatile("cp.async.cg.shared.global [%0], [%1], 16;"
                 :: "r"(dst), "l"(src) : "memory");
}
#define CP_COMMIT() asm volatile("cp.async.commit_group;" ::: "memory")
#define CP_WAIT1()  asm volatile("cp.async.wait_group 1;" ::: "memory")
#define CP_WAIT0()  asm volatile("cp.async.wait_group 0;" ::: "memory")

// e4m3x2 pack: low byte = a, high byte = b (RNE, saturate to +-448)
DINL uint16_t cvt2_e4m3(float a, float b) {
    uint16_t r;
    asm("cvt.rn.satfinite.e4m3x2.f32 %0, %1, %2;" : "=h"(r) : "f"(b), "f"(a));
    return r;
}

DINL void ldsm_x4(uint32_t* r, uint32_t addr) {
    asm volatile("ldmatrix.sync.aligned.m8n8.x4.shared.b16 {%0,%1,%2,%3}, [%4];"
        : "=r"(r[0]), "=r"(r[1]), "=r"(r[2]), "=r"(r[3]) : "r"(addr));
}

// fp8 warp MMA (base ISA): D(16x8,f32) += A(16x32,e4m3) * B(32x8,e4m3)
DINL void mma_fp8(float* d, const uint32_t* a, const uint32_t* b) {
    asm volatile(
        "mma.sync.aligned.m16n8k32.row.col.f32.e4m3.e4m3.f32 "
        "{%0,%1,%2,%3}, {%4,%5,%6,%7}, {%8,%9}, {%0,%1,%2,%3};"
        : "+f"(d[0]), "+f"(d[1]), "+f"(d[2]), "+f"(d[3])
        : "r"(a[0]), "r"(a[1]), "r"(a[2]), "r"(a[3]), "r"(b[0]), "r"(b[1]));
}
// zero-C variant: D = A*B; zeros passed as operands so ptxas can use RZ
DINL void mma_fp8_zc(float* d, const uint32_t* a, const uint32_t* b) {
    asm volatile(
        "mma.sync.aligned.m16n8k32.row.col.f32.e4m3.e4m3.f32 "
        "{%0,%1,%2,%3}, {%4,%5,%6,%7}, {%8,%9}, {%10,%11,%12,%13};"
        : "=f"(d[0]), "=f"(d[1]), "=f"(d[2]), "=f"(d[3])
        : "r"(a[0]), "r"(a[1]), "r"(a[2]), "r"(a[3]), "r"(b[0]), "r"(b[1]),
          "f"(0.0f), "f"(0.0f), "f"(0.0f), "f"(0.0f));
}

// ---- packed f32x2 ----
DINL unsigned long long splat2(float a) {
    unsigned long long r;
    asm("mov.b64 %0, {%1, %1};" : "=l"(r) : "f"(a));
    return r;
}
DINL unsigned long long mul2(unsigned long long a, unsigned long long b) {
    unsigned long long r;
    asm("mul.rn.f32x2 %0, %1, %2;" : "=l"(r) : "l"(a), "l"(b));
    return r;
}
DINL void fma2(unsigned long long& d, unsigned long long c, float x, float y) {
    asm("{\n\t.reg .b64 B;\n\tmov.b64 B, {%2, %3};\n\t"
        "fma.rn.f32x2 %0, %1, B, %0;\n\t}"
        : "+l"(d) : "l"(c), "f"(x), "f"(y));
}
DINL void unpack2(unsigned long long v, float& lo, float& hi) {
    asm("mov.b64 {%0, %1}, %2;" : "=f"(lo), "=f"(hi) : "l"(v));
}

#define SW128B(off) ((off) ^ (((off) >> 3) & 0x70))

// ============================================================================
// Kernel 1: blockwise fp8 quant of activations along K (one warp per block)
// ============================================================================
__global__ void __launch_bounds__(256)
quant_rows_kernel(const float* __restrict__ x, int K,
                  uint8_t* __restrict__ xq, float* __restrict__ sx, int Mtot) {
    int gw = blockIdx.x * 8 + (threadIdx.x >> 5);
    int lane = threadIdx.x & 31;
    int KB = K / 128;
    int m = gw / KB, kb = gw % KB;
    if (m >= Mtot) return;
    const float4 v = *(const float4*)(x + (size_t)m * K + kb * 128 + lane * 4);
    float mx = fmaxf(fmaxf(fabsf(v.x), fabsf(v.y)), fmaxf(fabsf(v.z), fabsf(v.w)));
    #pragma unroll
    for (int o = 16; o; o >>= 1) mx = fmaxf(mx, __shfl_xor_sync(0xffffffffu, mx, o));
    float scale = __fdiv_rn(fmaxf(mx, 1e-12f), 448.0f);
    uint16_t lo = cvt2_e4m3(__fdiv_rn(v.x, scale), __fdiv_rn(v.y, scale));
    uint16_t hi = cvt2_e4m3(__fdiv_rn(v.z, scale), __fdiv_rn(v.w, scale));
    *(uint32_t*)(xq + (size_t)m * K + kb * 128 + lane * 4) =
        (uint32_t)lo | ((uint32_t)hi << 16);
    if (lane == 0) sx[(size_t)kb * Mtot + m] = scale;
}

// ============================================================================
// Kernel 2: blockwise fp8 quant of weights along K (axis 0) + transpose.
//   W [K, N] f32 -> wq [n][k] bytes, sw [kb][n]
// ============================================================================
static constexpr int QW_WF   = 0;                       // float [128][132]
static constexpr int QW_PM   = 128 * 132 * 4;           // float [2][128]
static constexpr int QW_SCL  = QW_PM + 256 * 4;         // float [128]
static constexpr int QW_BT   = QW_SCL + 128 * 4;        // u32   [128][33]
static constexpr int QW_SMEM = QW_BT + 128 * 33 * 4;    // 86016

__global__ void __launch_bounds__(256)
quant_wt_kernel(const float* __restrict__ w, int K, int N,
                uint8_t* __restrict__ wq, float* __restrict__ sw) {
    extern __shared__ __align__(16) uint8_t qsm[];
    float* wf  = (float*)(qsm + QW_WF);
    float* pm  = (float*)(qsm + QW_PM);
    float* scl = (float*)(qsm + QW_SCL);
    uint32_t* bt = (uint32_t*)(qsm + QW_BT);
    const int kb = blockIdx.y, n0 = blockIdx.x * 128;
    const int tid = threadIdx.x;
    const float* src = w + (size_t)(kb * 128) * N + n0;

    #pragma unroll
    for (int i = 0; i < 16; i++) {
        int ch = i * 256 + tid;
        int k = ch >> 5, nc = ch & 31;
        cp16(smem_u32(wf + k * 132 + nc * 4), src + (size_t)k * N + nc * 4);
    }
    CP_COMMIT();
    CP_WAIT0();
    __syncthreads();

    const int c = tid & 127, h = tid >> 7;
    float mx = 0.f;
    for (int k = h * 64; k < h * 64 + 64; k++)
        mx = fmaxf(mx, fabsf(wf[k * 132 + c]));
    pm[h * 128 + c] = mx;
    __syncthreads();
    if (tid < 128) {
        float s = __fdiv_rn(fmaxf(fmaxf(pm[tid], pm[128 + tid]), 1e-12f), 448.0f);
        scl[tid] = s;
        sw[(size_t)kb * N + n0 + tid] = s;
    }
    __syncthreads();
    float s = scl[c];
    uint8_t* btb = (uint8_t*)bt;
    for (int k = h * 64; k < h * 64 + 64; k++)
        btb[c * 132 + k] = (uint8_t)cvt2_e4m3(__fdiv_rn(wf[k * 132 + c], s), 0.f);
    __syncthreads();
    #pragma unroll
    for (int i = 0; i < 16; i++) {
        int idx = i * 256 + tid;
        int r = idx >> 5, wd = idx & 31;
        ((uint32_t*)(wq + (size_t)(n0 + r) * K + (size_t)kb * 128))[wd] = bt[r * 33 + wd];
    }
}

// ============================================================================
// GEMM: BM x BN tile, NTHREADS threads (warp grid (BM/32) x (BN/32), 32x32
// per warp), mma.sync fp8, 3-stage cp.async pipeline, ONE __syncthreads per
// K-block, scales staged via cp.async, prefetch under ks=0 MMA shadow.
// EPI=0: out_f = C + bias.
// EPI=1 (BM=64,BN=128,NTHREADS=256): h=gelu(C+bias) -> fp8 quant out_q/out_s.
// ============================================================================
static constexpr int NSTAGE = 3;
static constexpr int SM_HDR = 1024;            // [64..576) bias

__host__ __device__ constexpr int stage_bytes(int BM, int BN) {
    return (((BM + BN) * 128 + (BM + BN) * 4 + 1023) / 1024) * 1024;
}
__host__ __device__ constexpr int smem_gemm(int BM, int BN) {
    return SM_HDR + NSTAGE * stage_bytes(BM, BN);
}

template <int EPI, int BM, int BN, int NTHREADS, int MINCTA>
__global__ void __launch_bounds__(NTHREADS, MINCTA)
gemm_kernel(const uint8_t* __restrict__ Aq, const float* __restrict__ sA,
            const uint8_t* __restrict__ Bq, const float* __restrict__ sB,
            const float* __restrict__ bias, int K, int N,
            float* __restrict__ out_f,
            uint8_t* __restrict__ out_q, float* __restrict__ out_s) {
    constexpr int WM = BM / 32;                 // warps along M
    constexpr int STAGE = stage_bytes(BM, BN);
    constexpr int SM_B  = BM * 128;
    constexpr int SM_SA = (BM + BN) * 128;
    constexpr int SM_SB = SM_SA + BM * 4;
    constexpr int RPP = NTHREADS / 8;           // tile rows loaded per pass

    extern __shared__ __align__(1024) uint8_t smem[];
    const uint32_t sbase = smem_u32(smem);
    const int tid = threadIdx.x;
    const int wid = tid >> 5, lane = tid & 31;
    const int wm = wid % WM, wn = wid / WM;
    const int g = lane >> 2, tig = lane & 3;
    const int n0 = blockIdx.x * BN, m0 = blockIdx.y * BM;
    const int NKB = K / 128;

    if (tid < BN) *(float*)(smem + 64 + tid * 4) = bias[n0 + tid];

    unsigned long long accp[2][4][2];
    #pragma unroll
    for (int mt = 0; mt < 2; mt++)
        #pragma unroll
        for (int nt = 0; nt < 4; nt++)
            #pragma unroll
            for (int p = 0; p < 2; p++) accp[mt][nt][p] = 0ull;

    // ---- pointer-increment prefetch state ----
    const int prow = tid >> 3, pcol = tid & 7;   // rows prow + RPP*i
    const uint8_t* pA = Aq + (size_t)(m0 + prow) * K + pcol * 16;
    const uint8_t* pB = Bq + (size_t)(n0 + prow) * K + pcol * 16;
    const float* psAg = sA + m0 + tid * 4;                       // tid < BM/4
    const float* psBg = sB + n0 + (tid - NTHREADS / 2) * 4;      // second half
    uint32_t swA[BM / RPP], swB[BN / RPP];
    #pragma unroll
    for (int i = 0; i < BM / RPP; i++)
        swA[i] = SW128B((uint32_t)((prow + RPP * i) * 128 + pcol * 16));
    #pragma unroll
    for (int i = 0; i < BN / RPP; i++)
        swB[i] = SW128B((uint32_t)((prow + RPP * i) * 128 + pcol * 16));

    auto prefetch = [&](int stg) {
        uint32_t st = sbase + SM_HDR + stg * STAGE;
        #pragma unroll
        for (int i = 0; i < BM / RPP; i++)
            cp16(st + swA[i], pA + (size_t)(RPP * i) * K);
        #pragma unroll
        for (int i = 0; i < BN / RPP; i++)
            cp16(st + SM_B + swB[i], pB + (size_t)(RPP * i) * K);
        if (tid < BM / 4)
            cp16(st + SM_SA + tid * 16, psAg);
        else if (tid >= NTHREADS / 2 && tid < NTHREADS / 2 + BN / 4)
            cp16(st + SM_SB + (tid - NTHREADS / 2) * 16, psBg);
        pA += 128; pB += 128; psAg += MROWS; psBg += N;
    };

    prefetch(0); CP_COMMIT();
    prefetch(1); CP_COMMIT();

    // ---- precombined ldmatrix offsets (stage-relative, row+swizzled-col) ----
    const int a_q = lane >> 3;
    const int rl  = lane & 7;
    uint32_t offA[2][4], offB[2][4];
    #pragma unroll
    for (int mt = 0; mt < 2; mt++) {
        uint32_t rowA = (uint32_t)((wm * 32 + mt * 16 + (a_q & 1) * 8 + rl) * 128);
        #pragma unroll
        for (int ks = 0; ks < 4; ks++)
            offA[mt][ks] = rowA + (uint32_t)((ks * 32 + (a_q >> 1) * 16) ^ (rl << 4));
    }
    // B pairs: x4 load np covers n-rows [np*16, np*16+16) of the warp block
    #pragma unroll
    for (int np = 0; np < 2; np++) {
        uint32_t rowB = (uint32_t)((wn * 32 + np * 16 + ((lane >> 4) & 1) * 8 + rl) * 128);
        #pragma unroll
        for (int ks = 0; ks < 4; ks++)
            offB[np][ks] = rowB + (uint32_t)((ks * 32 + ((lane >> 3) & 1) * 16) ^ (rl << 4));
    }

    int sidx = 0;   // stage holding current kb
    for (int kb = 0; kb < NKB; kb++) {
        const uint32_t stA = sbase + SM_HDR + sidx * STAGE;
        const uint32_t stB = stA + SM_B;

        CP_WAIT1();          // stage kb landed (group kb+1 may still be in flight)
        __syncthreads();     // all warps see stage kb; implies all finished kb-1

        float D[2][4][4];
        // ---- ks = 0: fragments + MMAs first, then prefetch under their shadow
        {
            uint32_t af[2][4], bq[2][4];
            #pragma unroll
            for (int mt = 0; mt < 2; mt++) ldsm_x4(af[mt], stA + offA[mt][0]);
            #pragma unroll
            for (int np = 0; np < 2; np++) ldsm_x4(bq[np], stB + offB[np][0]);
            #pragma unroll
            for (int mt = 0; mt < 2; mt++)
                #pragma unroll
                for (int nt = 0; nt < 4; nt++)
                    mma_fp8_zc(D[mt][nt], af[mt], &bq[nt >> 1][(nt & 1) * 2]);

            // prefetch kb+2 into slot (kb+2)%3 == (kb-1)%3 — free after the sync
            int sidx2 = sidx + 2 >= NSTAGE ? sidx + 2 - NSTAGE : sidx + 2;
            if (kb + 2 < NKB) prefetch(sidx2);
            CP_COMMIT();     // unconditional: uniform wait_group accounting
        }
        // ---- ks = 1..3
        #pragma unroll
        for (int ks = 1; ks < 4; ks++) {
            uint32_t af[2][4], bq[2][4];
            #pragma unroll
            for (int mt = 0; mt < 2; mt++) ldsm_x4(af[mt], stA + offA[mt][ks]);
            #pragma unroll
            for (int np = 0; np < 2; np++) ldsm_x4(bq[np], stB + offB[np][ks]);
            #pragma unroll
            for (int mt = 0; mt < 2; mt++)
                #pragma unroll
                for (int nt = 0; nt < 4; nt++)
                    mma_fp8(D[mt][nt], af[mt], &bq[nt >> 1][(nt & 1) * 2]);
        }

        // fine-grained scale promotion (packed f32x2): acc += (sa*sb) * D
        const uint8_t* sAs = smem + SM_HDR + sidx * STAGE + SM_SA;
        const uint8_t* sBs = smem + SM_HDR + sidx * STAGE + SM_SB;
        unsigned long long SB2[4], saS[2][2];
        #pragma unroll
        for (int nt = 0; nt < 4; nt++)
            SB2[nt] = *(const unsigned long long*)(sBs + (wn * 32 + nt * 8 + tig * 2) * 4);
        #pragma unroll
        for (int mt = 0; mt < 2; mt++)
            #pragma unroll
            for (int j = 0; j < 2; j++)
                saS[mt][j] = splat2(*(const float*)(sAs + (wm * 32 + mt * 16 + j * 8 + g) * 4));
        #pragma unroll
        for (int mt = 0; mt < 2; mt++)
            #pragma unroll
            for (int nt = 0; nt < 4; nt++) {
                unsigned long long c01 = mul2(saS[mt][0], SB2[nt]);
                unsigned long long c23 = mul2(saS[mt][1], SB2[nt]);
                fma2(accp[mt][nt][0], c01, D[mt][nt][0], D[mt][nt][1]);
                fma2(accp[mt][nt][1], c23, D[mt][nt][2], D[mt][nt][3]);
            }

        sidx = sidx + 1 >= NSTAGE ? 0 : sidx + 1;
    }
    __syncthreads();   // mainloop smem dead; epilogue reuses it

    // ------------------------- epilogue -------------------------
    constexpr int FBS = BM + 1;                 // fb stride ([col][row])
    float* fb = (float*)(smem + SM_HDR);
    const float* biasS = (const float*)(smem + 64);
    #pragma unroll
    for (int mt = 0; mt < 2; mt++)
        #pragma unroll
        for (int nt = 0; nt < 4; nt++)
            #pragma unroll
            for (int p = 0; p < 2; p++) {
                float lo, hi;
                unpack2(accp[mt][nt][p], lo, hi);
                int row = wm * 32 + mt * 16 + p * 8 + g;
                int c0 = wn * 32 + nt * 8 + tig * 2;
                #pragma unroll
                for (int e = 0; e < 2; e++) {
                    int col = c0 + e;
                    float u = (e ? hi : lo) + biasS[col];
                    float v;
                    if (EPI == 1) {
                        float t = 0.7978845608028654f * (u + 0.044715f * u * u * u);
                        v = 0.5f * u * (1.0f + tanhf(t));
                    } else {
                        v = u;
                    }
                    fb[col * FBS + row] = v;
                }
            }
    __syncthreads();

    if (EPI == 0) {
        #pragma unroll
        for (int i = 0; i < BM * BN / NTHREADS; i++) {
            int idx = i * NTHREADS + tid;
            int r = idx / BN, c = idx % BN;
            out_f[(size_t)(m0 + r) * N + n0 + c] = fb[c * FBS + r];
        }
    } else {
        // BM=64, BN=128, NTHREADS=256: blockwise re-quant of h along 128 cols
        uint32_t* bt = (uint32_t*)(smem + SM_HDR + 128 * FBS * 4);     // [64][33]
        float* pm = (float*)((uint8_t*)bt + 64 * 33 * 4);              // [4][64]+[64]
        const int r = tid & 63, q = tid >> 6;        // 4 col-segments of 32
        float mx = 0.f;
        #pragma unroll
        for (int c = q * 32; c < q * 32 + 32; c++) mx = fmaxf(mx, fabsf(fb[c * FBS + r]));
        pm[q * 64 + r] = mx;
        __syncthreads();
        if (tid < 64) {
            float m01 = fmaxf(pm[tid], pm[64 + tid]);
            float m23 = fmaxf(pm[128 + tid], pm[192 + tid]);
            float sc = __fdiv_rn(fmaxf(fmaxf(m01, m23), 1e-12f), 448.0f);
            pm[256 + tid] = sc;
            out_s[(size_t)(n0 >> 7) * MROWS + m0 + tid] = sc;
        }
        __syncthreads();
        float sc = pm[256 + r];
        #pragma unroll
        for (int c = q * 32; c < q * 32 + 32; c += 4) {
            uint16_t lo = cvt2_e4m3(__fdiv_rn(fb[(c + 0) * FBS + r], sc),
                                    __fdiv_rn(fb[(c + 1) * FBS + r], sc));
            uint16_t hi = cvt2_e4m3(__fdiv_rn(fb[(c + 2) * FBS + r], sc),
                                    __fdiv_rn(fb[(c + 3) * FBS + r], sc));
            bt[r * 33 + (c >> 2)] = (uint32_t)lo | ((uint32_t)hi << 16);
        }
        __syncthreads();
        // store 64 rows x 32 words, 8 per thread
        #pragma unroll
        for (int i = 0; i < 8; i++) {
            int idx = i * 256 + tid;
            int rr = idx >> 5, wd = idx & 31;
            ((uint32_t*)(out_q + (size_t)(m0 + rr) * N + n0))[wd] = bt[rr * 33 + wd];
        }
    }
}

// ============================================================================
// Launch
// ============================================================================
extern "C" void kernel_launch(void* const* d_in, const int* in_sizes, int n_in,
                              void* d_out, int out_size) {
    const float* x  = (const float*)d_in[0];
    const float* w1 = (const float*)d_in[1];
    const float* b1 = (const float*)d_in[2];
    const float* w2 = (const float*)d_in[3];
    const float* b2 = (const float*)d_in[4];
    float* out = (float*)d_out;

    constexpr int SMEM1 = smem_gemm(64, 128);   // 77824
    constexpr int SMEM2 = smem_gemm(64, 64);    // 53248

    cudaFuncSetAttribute((gemm_kernel<1, 64, 128, 256, 2>),
                         cudaFuncAttributeMaxDynamicSharedMemorySize, SMEM1);
    cudaFuncSetAttribute((gemm_kernel<0, 64, 64, 128, 4>),
                         cudaFuncAttributeMaxDynamicSharedMemorySize, SMEM2);
    cudaFuncSetAttribute(quant_wt_kernel,
                         cudaFuncAttributeMaxDynamicSharedMemorySize, QW_SMEM);

    uint8_t *xq, *w1q, *w2q, *hq;
    float *sx, *sw1, *sw2, *sh;
    cudaGetSymbolAddress((void**)&xq,  g_xq);
    cudaGetSymbolAddress((void**)&sx,  g_sx);
    cudaGetSymbolAddress((void**)&w1q, g_w1q);
    cudaGetSymbolAddress((void**)&sw1, g_sw1);
    cudaGetSymbolAddress((void**)&w2q, g_w2q);
    cudaGetSymbolAddress((void**)&sw2, g_sw2);
    cudaGetSymbolAddress((void**)&hq,  g_hq);
    cudaGetSymbolAddress((void**)&sh,  g_sh);

    // 1) quantize activations x
    quant_rows_kernel<<<(MROWS * (K1 / 128)) / 8, 256>>>(x, K1, xq, sx, MROWS);

    // 2) quantize + transpose weights (smem-staged single read)
    quant_wt_kernel<<<dim3(N1 / 128, K1 / 128), 256, QW_SMEM>>>(w1, K1, N1, w1q, sw1);
    quant_wt_kernel<<<dim3(N2 / 128, K2 / 128), 256, QW_SMEM>>>(w2, K2, N2, w2q, sw2);

    // 3) GEMM1 (64x128 tiles, 256 thr, 2 CTAs/SM) + bias + GELU + re-quant
    gemm_kernel<1, 64, 128, 256, 2><<<dim3(N1 / 128, MROWS / 64), 256, SMEM1>>>(
        xq, sx, w1q, sw1, b1, K1, N1, nullptr, hq, sh);

    // 4) GEMM2 (64x64 tiles, 128 thr, 4 CTAs/SM) + bias -> out
    gemm_kernel<0, 64, 64, 128, 4><<<dim3(N2 / 64, MROWS / 64), 128, SMEM2>>>(
        hq, sh, w2q, sw2, b2, K2, N2, out, nullptr, nullptr);
}